// round 9
// baseline (speedup 1.0000x reference)
#include <cuda_runtime.h>
#include <cuda_bf16.h>
#include <cstdint>
#include <math.h>

#define LQ   256
#define DHH  64
#define NH   8
#define NM   64
#define NSL  (NH*NM)   // 512
#define DMOD 512
#define NTOK (NM*LQ)   // 16384

// ---------------- scratch -------------
__device__ float g_e2[LQ * NSL * LQ];        // [i][hm][j]
__device__ float g_z1[NSL * LQ * DHH];       // [hm][i][d]
__device__ float g_z2[LQ * NH * DHH];        // [i][h][d]
__device__ float g_invl[NSL * LQ];           // [hm][i]

__device__ __nv_bfloat16 g_xhi[NTOK * DMOD];
__device__ __nv_bfloat16 g_xlo[NTOK * DMOD];
__device__ __nv_bfloat16 g_whi[3 * DMOD * DMOD];
__device__ __nv_bfloat16 g_wlo[3 * DMOD * DMOD];
__device__ __nv_bfloat16 g_qhi[NSL * LQ * DHH];
__device__ __nv_bfloat16 g_qlo[NSL * LQ * DHH];
__device__ __nv_bfloat16 g_khi[NSL * LQ * DHH];
__device__ __nv_bfloat16 g_klo[NSL * LQ * DHH];
__device__ __nv_bfloat16 g_vhi[NSL * LQ * DHH];
__device__ __nv_bfloat16 g_vlo[NSL * LQ * DHH];
__device__ __nv_bfloat16 g_akhi[LQ * LQ * DHH];
__device__ __nv_bfloat16 g_aklo[LQ * LQ * DHH];
__device__ __nv_bfloat16 g_avhi[LQ * LQ * DHH];
__device__ __nv_bfloat16 g_avlo[LQ * LQ * DHH];
__device__ __nv_bfloat16 g_ahi[LQ * NSL * LQ];   // unnormalized p hi [i][hm][j]
__device__ __nv_bfloat16 g_alo[LQ * NSL * LQ];

// ========================= helpers ==================================
__device__ __forceinline__ uint32_t smem_to_u32(const void* p) {
    uint32_t a;
    asm("{ .reg .u64 t; cvta.to.shared.u64 t, %1; cvt.u32.u64 %0, t; }"
        : "=r"(a) : "l"(p));
    return a;
}
__device__ __forceinline__ void ldsm_x4(uint32_t addr, uint32_t* r) {
    asm volatile("ldmatrix.sync.aligned.m8n8.x4.shared.b16 {%0,%1,%2,%3}, [%4];"
        : "=r"(r[0]), "=r"(r[1]), "=r"(r[2]), "=r"(r[3]) : "r"(addr));
}
__device__ __forceinline__ void ldsm_x4_t(uint32_t addr, uint32_t* r) {
    asm volatile("ldmatrix.sync.aligned.m8n8.x4.trans.shared.b16 {%0,%1,%2,%3}, [%4];"
        : "=r"(r[0]), "=r"(r[1]), "=r"(r[2]), "=r"(r[3]) : "r"(addr));
}
__device__ __forceinline__ void mma_bf16(float* c, const uint32_t* a,
                                         const uint32_t* b) {
    asm volatile(
        "mma.sync.aligned.m16n8k16.row.col.f32.bf16.bf16.f32 "
        "{%0,%1,%2,%3}, {%4,%5,%6,%7}, {%8,%9}, {%0,%1,%2,%3};"
        : "+f"(c[0]), "+f"(c[1]), "+f"(c[2]), "+f"(c[3])
        : "r"(a[0]), "r"(a[1]), "r"(a[2]), "r"(a[3]), "r"(b[0]), "r"(b[1]));
}
__device__ __forceinline__ uint32_t pack_bf16(float a, float b) {
    __nv_bfloat162 h(__float2bfloat16(a), __float2bfloat16(b));
    return *(uint32_t*)&h;
}
__device__ __forceinline__ void cp16(uint32_t s, const void* g) {
    asm volatile("cp.async.cg.shared.global [%0], [%1], 16;"
                 :: "r"(s), "l"(g) : "memory");
}
#define CP_COMMIT() asm volatile("cp.async.commit_group;" ::: "memory")
#define CP_WAIT(n)  asm volatile("cp.async.wait_group %0;" :: "n"(n) : "memory")

// ============================================================================
// merged split
// ============================================================================
struct SplitArgs {
    const float* src[6];
    __nv_bfloat16* hi[6];
    __nv_bfloat16* lo[6];
    int off[7];
};

__global__ __launch_bounds__(256) void split_all_kernel(SplitArgs a)
{
    int total = a.off[6];
    for (int idx = blockIdx.x * 256 + threadIdx.x; idx < total;
         idx += gridDim.x * 256) {
        int seg = 0;
#pragma unroll
        for (int s = 1; s < 6; s++) if (idx >= a.off[s]) seg = s;
        int li = idx - a.off[seg];
        float4 v = *(const float4*)&a.src[seg][li * 4];
        __nv_bfloat16 h0 = __float2bfloat16(v.x);
        __nv_bfloat16 h1 = __float2bfloat16(v.y);
        __nv_bfloat16 h2 = __float2bfloat16(v.z);
        __nv_bfloat16 h3 = __float2bfloat16(v.w);
        __nv_bfloat162 hp0(h0, h1), hp1(h2, h3);
        __nv_bfloat162 lp0(__float2bfloat16(v.x - __bfloat162float(h0)),
                           __float2bfloat16(v.y - __bfloat162float(h1)));
        __nv_bfloat162 lp1(__float2bfloat16(v.z - __bfloat162float(h2)),
                           __float2bfloat16(v.w - __bfloat162float(h3)));
        *(__nv_bfloat162*)&a.hi[seg][li * 4]     = hp0;
        *(__nv_bfloat162*)&a.hi[seg][li * 4 + 2] = hp1;
        *(__nv_bfloat162*)&a.lo[seg][li * 4]     = lp0;
        *(__nv_bfloat162*)&a.lo[seg][li * 4 + 2] = lp1;
    }
}

// ============================================================================
// K1: projection GEMM (unchanged)
// ============================================================================
#define PMAT  (128 * 80)
#define PSTG  (4 * PMAT)
#define P_TOT (2 * PSTG)      // 81920

__global__ __launch_bounds__(256) void proj_mma_kernel()
{
    extern __shared__ __align__(16) unsigned char dsm[];
    const uint32_t sb = smem_to_u32(dsm);

    const int tid = threadIdx.x, lane = tid & 31, wid = tid >> 5;
    const int t0 = blockIdx.x * 128;
    const int n0 = blockIdx.y * 128;
    const int sel = blockIdx.z;

    const __nv_bfloat16* Ah = g_xhi;
    const __nv_bfloat16* Al = g_xlo;
    const __nv_bfloat16* Bh = g_whi + sel * DMOD * DMOD;
    const __nv_bfloat16* Bl = g_wlo + sel * DMOD * DMOD;
    __nv_bfloat16 *hip, *lop;
    if (sel == 0)      { hip = g_qhi; lop = g_qlo; }
    else if (sel == 1) { hip = g_khi; lop = g_klo; }
    else               { hip = g_vhi; lop = g_vlo; }

    const int wm = (wid & 3) * 32;
    const int wn = (wid >> 2) * 64;
    const int lr  = (tid >> 2);
    const int seg = tid & 3;

    auto stage_load = [&](int ch, int st) {
        const int k0 = ch * 32;
        uint32_t s0 = sb + st * PSTG;
#pragma unroll
        for (int l = 0; l < 8; l++) {
            int mat = l >> 1;
            int r = (l & 1) * 64 + lr;
            const __nv_bfloat16* gp;
            int row;
            if (mat == 0)      { gp = Ah; row = t0 + r; }
            else if (mat == 1) { gp = Al; row = t0 + r; }
            else if (mat == 2) { gp = Bh; row = n0 + r; }
            else               { gp = Bl; row = n0 + r; }
            cp16(s0 + mat * PMAT + r * 80 + seg * 16,
                 &gp[row * DMOD + k0 + seg * 8]);
        }
    };

    float acc[2][8][4];
#pragma unroll
    for (int a = 0; a < 2; a++)
#pragma unroll
        for (int b = 0; b < 8; b++)
#pragma unroll
            for (int c = 0; c < 4; c++) acc[a][b][c] = 0.f;

    stage_load(0, 0);
    CP_COMMIT();

    for (int ch = 0; ch < 16; ch++) {
        const int st = ch & 1;
        if (ch + 1 < 16) { stage_load(ch + 1, st ^ 1); CP_COMMIT(); CP_WAIT(1); }
        else             { CP_WAIT(0); }
        __syncthreads();

        const uint32_t s0 = sb + st * PSTG;
#pragma unroll
        for (int s = 0; s < 2; s++) {
            uint32_t ah[2][4], al[2][4];
#pragma unroll
            for (int mi = 0; mi < 2; mi++) {
                int row = wm + mi * 16 + (lane & 15);
                uint32_t ad = s0 + row * 80 + s * 32 + ((lane >> 4) & 1) * 16;
                ldsm_x4(ad, ah[mi]);
                ldsm_x4(ad + PMAT, al[mi]);
            }
#pragma unroll
            for (int p = 0; p < 4; p++) {
                uint32_t bh[4], bl[4];
                int row = wn + p * 16 + (lane & 7) + ((lane >> 4) & 1) * 8;
                uint32_t bd = s0 + 2 * PMAT + row * 80 + s * 32 + ((lane >> 3) & 1) * 16;
                ldsm_x4(bd, bh);
                ldsm_x4(bd + PMAT, bl);
#pragma unroll
                for (int mi = 0; mi < 2; mi++)
#pragma unroll
                    for (int su = 0; su < 2; su++) {
                        mma_bf16(acc[mi][p * 2 + su], ah[mi], &bh[su * 2]);
                        mma_bf16(acc[mi][p * 2 + su], ah[mi], &bl[su * 2]);
                        mma_bf16(acc[mi][p * 2 + su], al[mi], &bh[su * 2]);
                    }
            }
        }
        __syncthreads();
    }

#pragma unroll
    for (int mi = 0; mi < 2; mi++)
#pragma unroll
        for (int ni = 0; ni < 8; ni++) {
            int e = n0 + wn + ni * 8 + (lane & 3) * 2;
            int h = e >> 6, d = e & 63;
#pragma unroll
            for (int rr = 0; rr < 2; rr++) {
                int t = t0 + wm + mi * 16 + (lane >> 2) + rr * 8;
                int m = t >> 8, i = t & 255;
                int idx = ((h * NM + m) * LQ + i) * DHH + d;
                float vx = acc[mi][ni][rr * 2 + 0];
                float vy = acc[mi][ni][rr * 2 + 1];
                __nv_bfloat16 h0 = __float2bfloat16(vx);
                __nv_bfloat16 h1 = __float2bfloat16(vy);
                __nv_bfloat162 hp(h0, h1);
                __nv_bfloat162 lp(__float2bfloat16(vx - __bfloat162float(h0)),
                                  __float2bfloat16(vy - __bfloat162float(h1)));
                *(__nv_bfloat162*)&hip[idx] = hp;
                *(__nv_bfloat162*)&lop[idx] = lp;
            }
        }
}

// ============================================================================
// K2: e2 (unchanged)
// ============================================================================
#define E2_AHI 0
#define E2_ASZ (128 * 144)
#define E2_B   (2 * E2_ASZ)
#define E2_TOT (4 * E2_ASZ)

__global__ __launch_bounds__(256) void e2_mma_kernel()
{
    extern __shared__ __align__(16) unsigned char dsm[];
    const uint32_t sb = smem_to_u32(dsm);

    const int tid = threadIdx.x, lane = tid & 31, wid = tid >> 5;
    const int hm0 = blockIdx.x * 128;
    const int j0  = blockIdx.y * 128;
    const int i   = blockIdx.z;
    const int wm = (wid & 3) * 32;
    const int wn = (wid >> 2) * 64;

#pragma unroll
    for (int l = 0; l < 4; l++) {
        int id = tid + l * 256;
        int r = id >> 3, c = id & 7;
        int ga = ((hm0 + r) * LQ + i) * DHH + c * 8;
        cp16(sb + E2_AHI + r * 144 + c * 16, &g_qhi[ga]);
        cp16(sb + E2_AHI + E2_ASZ + r * 144 + c * 16, &g_qlo[ga]);
        int gb = (i * LQ + j0 + r) * DHH + c * 8;
        cp16(sb + E2_B + r * 144 + c * 16, &g_akhi[gb]);
        cp16(sb + E2_B + E2_ASZ + r * 144 + c * 16, &g_aklo[gb]);
    }
    CP_COMMIT();
    CP_WAIT(0);
    __syncthreads();

    float acc[2][8][4];
#pragma unroll
    for (int a = 0; a < 2; a++)
#pragma unroll
        for (int b = 0; b < 8; b++)
#pragma unroll
            for (int c = 0; c < 4; c++) acc[a][b][c] = 0.f;

#pragma unroll
    for (int s = 0; s < 4; s++) {
        uint32_t ah[2][4], al[2][4];
#pragma unroll
        for (int mi = 0; mi < 2; mi++) {
            uint32_t ad = sb + E2_AHI + (wm + mi * 16 + (lane & 15)) * 144 +
                          s * 32 + ((lane >> 4) & 1) * 16;
            ldsm_x4(ad, ah[mi]);
            ldsm_x4(ad + E2_ASZ, al[mi]);
        }
#pragma unroll
        for (int p = 0; p < 4; p++) {
            uint32_t bh[4], bl[4];
            uint32_t bd = sb + E2_B + (wn + p * 16 + (lane & 7) + ((lane >> 4) & 1) * 8) * 144 +
                          s * 32 + ((lane >> 3) & 1) * 16;
            ldsm_x4(bd, bh);
            ldsm_x4(bd + E2_ASZ, bl);
#pragma unroll
            for (int mi = 0; mi < 2; mi++)
#pragma unroll
                for (int su = 0; su < 2; su++) {
                    mma_bf16(acc[mi][p * 2 + su], ah[mi], &bh[su * 2]);
                    mma_bf16(acc[mi][p * 2 + su], ah[mi], &bl[su * 2]);
                    mma_bf16(acc[mi][p * 2 + su], al[mi], &bh[su * 2]);
                }
        }
    }

#pragma unroll
    for (int mi = 0; mi < 2; mi++)
#pragma unroll
        for (int ni = 0; ni < 8; ni++) {
            int j = j0 + wn + ni * 8 + (lane & 3) * 2;
#pragma unroll
            for (int rr = 0; rr < 2; rr++) {
                int hm = hm0 + wm + mi * 16 + (lane >> 2) + rr * 8;
                *(float2*)&g_e2[(i * NSL + hm) * LQ + j] =
                    make_float2(acc[mi][ni][rr * 2 + 0], acc[mi][ni][rr * 2 + 1]);
            }
        }
}

// ============================================================================
// K3: fused attention; grid (hm, i-half). CTA = 128 q-rows, warp = 16 rows.
// smem: KV stage x2 | Q hi/lo (128 rows)
// ============================================================================
#define A3_KSZ  (64 * 144)           // 9216
#define A3_STG  (4 * A3_KSZ)         // 36864
#define A3_Q    (2 * A3_STG)         // 73728
#define A3_QSZ  (128 * 144)          // 18432
#define A3_TOT  (A3_Q + 2 * A3_QSZ)  // 110592

__global__ __launch_bounds__(256) void attn_mma_kernel()
{
    extern __shared__ __align__(16) unsigned char dsm[];
    const uint32_t sb = smem_to_u32(dsm);
    const int tid = threadIdx.x, lane = tid & 31, wid = tid >> 5;
    const int hm = blockIdx.x;
    const int i0 = blockIdx.y * 128;
    const int wm = wid * 16;
    const int gr = lane >> 2, qd = lane & 3;

    auto load_kv = [&](int jc, int st) {
        uint32_t s0 = sb + st * A3_STG;
#pragma unroll
        for (int l = 0; l < 2; l++) {
            int id = tid + l * 256;
            int r = id >> 3, c = id & 7;
            int gk = (hm * LQ + jc * 64 + r) * DHH + c * 8;
            cp16(s0 + 0 * A3_KSZ + r * 144 + c * 16, &g_khi[gk]);
            cp16(s0 + 1 * A3_KSZ + r * 144 + c * 16, &g_klo[gk]);
            cp16(s0 + 2 * A3_KSZ + r * 144 + c * 16, &g_vhi[gk]);
            cp16(s0 + 3 * A3_KSZ + r * 144 + c * 16, &g_vlo[gk]);
        }
    };

    // Q resident (128 rows)
#pragma unroll
    for (int l = 0; l < 4; l++) {
        int id = tid + l * 256;
        int r = id >> 3, c = id & 7;
        int gq = (hm * LQ + i0 + r) * DHH + c * 8;
        cp16(sb + A3_Q + r * 144 + c * 16, &g_qhi[gq]);
        cp16(sb + A3_Q + A3_QSZ + r * 144 + c * 16, &g_qlo[gq]);
    }
    CP_COMMIT();
    load_kv(0, 0);
    CP_COMMIT();

    float accz[8][4];
#pragma unroll
    for (int b = 0; b < 8; b++)
#pragma unroll
        for (int c = 0; c < 4; c++) accz[b][c] = 0.f;
    float rsum[2] = {0.f, 0.f};

    for (int jc = 0; jc < 4; jc++) {
        const int st = jc & 1;
        __syncthreads();
        if (jc < 3) { load_kv(jc + 1, st ^ 1); CP_COMMIT(); CP_WAIT(1); }
        else        { CP_WAIT(0); }
        __syncthreads();

        const uint32_t s0 = sb + st * A3_STG;

        // ---- scores: e1 = q k^T ----
        float acc[8][4];
#pragma unroll
        for (int b = 0; b < 8; b++)
#pragma unroll
            for (int c = 0; c < 4; c++) acc[b][c] = 0.f;

#pragma unroll
        for (int s = 0; s < 4; s++) {
            uint32_t ah[4], al[4];
            uint32_t ad = sb + A3_Q + (wm + (lane & 15)) * 144 +
                          s * 32 + ((lane >> 4) & 1) * 16;
            ldsm_x4(ad, ah);
            ldsm_x4(ad + A3_QSZ, al);
#pragma unroll
            for (int p = 0; p < 4; p++) {
                uint32_t bh[4], bl[4];
                uint32_t bd = s0 + (p * 16 + (lane & 7) + ((lane >> 4) & 1) * 8) * 144 +
                              s * 32 + ((lane >> 3) & 1) * 16;
                ldsm_x4(bd, bh);
                ldsm_x4(bd + A3_KSZ, bl);
#pragma unroll
                for (int su = 0; su < 2; su++) {
                    mma_bf16(acc[p * 2 + su], ah, &bh[su * 2]);
                    mma_bf16(acc[p * 2 + su], ah, &bl[su * 2]);
                    mma_bf16(acc[p * 2 + su], al, &bh[su * 2]);
                }
            }
        }

        // ---- + e2, scale, exp, rowsum, pack p hi/lo ----
        uint32_t phh[8][2], pll[8][2];
        {
            int ir0 = i0 + wm + gr;
            float2 e2b0[8], e2b1[8];
#pragma unroll
            for (int ni = 0; ni < 8; ni++) {
                int col = jc * 64 + ni * 8 + qd * 2;
                e2b0[ni] = *(const float2*)&g_e2[(ir0 * NSL + hm) * LQ + col];
                e2b1[ni] = *(const float2*)&g_e2[((ir0 + 8) * NSL + hm) * LQ + col];
            }
#pragma unroll
            for (int ni = 0; ni < 8; ni++) {
                int col = jc * 64 + ni * 8 + qd * 2;
                float e0 = __expf((acc[ni][0] + e2b0[ni].x) * 0.125f);
                float e1 = __expf((acc[ni][1] + e2b0[ni].y) * 0.125f);
                float e2v = __expf((acc[ni][2] + e2b1[ni].x) * 0.125f);
                float e3 = __expf((acc[ni][3] + e2b1[ni].y) * 0.125f);
                rsum[0] += e0 + e1;
                rsum[1] += e2v + e3;
                uint32_t h01 = pack_bf16(e0, e1);
                uint32_t h23 = pack_bf16(e2v, e3);
                __nv_bfloat162 hh01 = *(__nv_bfloat162*)&h01;
                __nv_bfloat162 hh23 = *(__nv_bfloat162*)&h23;
                uint32_t l01 = pack_bf16(e0 - __bfloat162float(hh01.x),
                                         e1 - __bfloat162float(hh01.y));
                uint32_t l23 = pack_bf16(e2v - __bfloat162float(hh23.x),
                                         e3 - __bfloat162float(hh23.y));
                phh[ni][0] = h01; phh[ni][1] = h23;
                pll[ni][0] = l01; pll[ni][1] = l23;
                *(uint32_t*)&g_ahi[(ir0 * NSL + hm) * LQ + col] = h01;
                *(uint32_t*)&g_ahi[((ir0 + 8) * NSL + hm) * LQ + col] = h23;
                *(uint32_t*)&g_alo[(ir0 * NSL + hm) * LQ + col] = l01;
                *(uint32_t*)&g_alo[((ir0 + 8) * NSL + hm) * LQ + col] = l23;
            }
        }

        // ---- z1 += p V ----
#pragma unroll
        for (int s = 0; s < 4; s++) {
            uint32_t Ahf[4] = {phh[2 * s][0], phh[2 * s][1],
                               phh[2 * s + 1][0], phh[2 * s + 1][1]};
            uint32_t Alf[4] = {pll[2 * s][0], pll[2 * s][1],
                               pll[2 * s + 1][0], pll[2 * s + 1][1]};
#pragma unroll
            for (int p = 0; p < 4; p++) {
                uint32_t bh[4], bl[4];
                uint32_t bd = s0 + 2 * A3_KSZ + (s * 16 + (lane & 15)) * 144 +
                              p * 32 + ((lane >> 4) & 1) * 16;
                ldsm_x4_t(bd, bh);
                ldsm_x4_t(bd + A3_KSZ, bl);
#pragma unroll
                for (int su = 0; su < 2; su++) {
                    mma_bf16(accz[p * 2 + su], Ahf, &bh[su * 2]);
                    mma_bf16(accz[p * 2 + su], Ahf, &bl[su * 2]);
                    mma_bf16(accz[p * 2 + su], Alf, &bh[su * 2]);
                }
            }
        }
    }

    // ---- finalize ----
    float inv[2];
#pragma unroll
    for (int rr = 0; rr < 2; rr++) {
        float r = rsum[rr];
        r += __shfl_xor_sync(0xffffffffu, r, 1);
        r += __shfl_xor_sync(0xffffffffu, r, 2);
        inv[rr] = 1.f / r;
    }
    if (qd == 0) {
#pragma unroll
        for (int rr = 0; rr < 2; rr++)
            g_invl[hm * LQ + i0 + wm + gr + rr * 8] = inv[rr];
    }
#pragma unroll
    for (int ni = 0; ni < 8; ni++)
#pragma unroll
        for (int rr = 0; rr < 2; rr++) {
            int ir = i0 + wm + gr + rr * 8;
            int d = ni * 8 + qd * 2;
            *(float2*)&g_z1[(hm * LQ + ir) * DHH + d] =
                make_float2(accz[ni][rr * 2 + 0] * inv[rr],
                            accz[ni][rr * 2 + 1] * inv[rr]);
        }
}

// ============================================================================
// K4: z2 GEMM; grid (4 hm-quarters, i). CTA = 128 rows, warp = 16 rows.
// stage: Ahi(18432)|Alo(18432)|KVhi(9216)|KVlo(9216) = 55296, x2 + linv
// ============================================================================
#define Z3_ASZ  (128 * 144)                  // 18432
#define Z3_KVSZ (64 * 144)                   // 9216
#define Z3_STG  (2 * Z3_ASZ + 2 * Z3_KVSZ)   // 55296
#define Z3_LINV (2 * Z3_STG)                 // 110592
#define Z3_TOT  (Z3_LINV + 512)              // 111104

__global__ __launch_bounds__(256) void z2_mma_kernel()
{
    extern __shared__ __align__(16) unsigned char dsm[];
    const uint32_t sb = smem_to_u32(dsm);
    const int tid = threadIdx.x, lane = tid & 31, wid = tid >> 5;
    const int hm0 = blockIdx.x * 128;
    const int i = blockIdx.y;
    const int wm = wid * 16;
    float* linv = (float*)(dsm + Z3_LINV);

    if (tid < 128) linv[tid] = g_invl[(hm0 + tid) * LQ + i];

    auto load_chunk = [&](int jc, int st) {
        uint32_t s0 = sb + st * Z3_STG;
#pragma unroll
        for (int l = 0; l < 4; l++) {
            int id = tid + l * 256;
            int r = id >> 3, c = id & 7;
            int ga = (i * NSL + hm0 + r) * LQ + jc * 64 + c * 8;
            cp16(s0 + r * 144 + c * 16, &g_ahi[ga]);
            cp16(s0 + Z3_ASZ + r * 144 + c * 16, &g_alo[ga]);
        }
#pragma unroll
        for (int l = 0; l < 2; l++) {
            int id = tid + l * 256;
            int r = id >> 3, c = id & 7;
            int gb = (i * LQ + jc * 64 + r) * DHH + c * 8;
            cp16(s0 + 2 * Z3_ASZ + r * 144 + c * 16, &g_avhi[gb]);
            cp16(s0 + 2 * Z3_ASZ + Z3_KVSZ + r * 144 + c * 16, &g_avlo[gb]);
        }
    };

    load_chunk(0, 0);
    CP_COMMIT();

    float acc[8][4];
#pragma unroll
    for (int b = 0; b < 8; b++)
#pragma unroll
        for (int c = 0; c < 4; c++) acc[b][c] = 0.f;

    for (int jc = 0; jc < 4; jc++) {
        const int st = jc & 1;
        __syncthreads();
        if (jc < 3) { load_chunk(jc + 1, st ^ 1); CP_COMMIT(); CP_WAIT(1); }
        else        { CP_WAIT(0); }
        __syncthreads();

        const uint32_t s0 = sb + st * Z3_STG;
#pragma unroll
        for (int s = 0; s < 4; s++) {
            uint32_t ah[4], al[4];
            uint32_t ad = s0 + (wm + (lane & 15)) * 144 +
                          s * 32 + ((lane >> 4) & 1) * 16;
            ldsm_x4(ad, ah);
            ldsm_x4(ad + Z3_ASZ, al);
#pragma unroll
            for (int p = 0; p < 4; p++) {
                uint32_t bh[4], bl[4];
                uint32_t bd = s0 + 2 * Z3_ASZ + (s * 16 + (lane & 15)) * 144 +
                              p * 32 + ((lane >> 4) & 1) * 16;
                ldsm_x4_t(bd, bh);
                ldsm_x4_t(bd + Z3_KVSZ, bl);
#pragma unroll
                for (int su = 0; su < 2; su++) {
                    mma_bf16(acc[p * 2 + su], ah, &bh[su * 2]);
                    mma_bf16(acc[p * 2 + su], ah, &bl[su * 2]);
                    mma_bf16(acc[p * 2 + su], al, &bh[su * 2]);
                }
            }
        }
    }

    // reduce over m (2 h-groups of 64) with invl scaling
    __syncthreads();
    float* Sf = (float*)dsm;   // [128][65]
#pragma unroll
    for (int ni = 0; ni < 8; ni++)
#pragma unroll
        for (int rr = 0; rr < 2; rr++) {
            int r = wm + (lane >> 2) + rr * 8;
            int c = ni * 8 + (lane & 3) * 2;
            Sf[r * 65 + c]     = acc[ni][rr * 2 + 0];
            Sf[r * 65 + c + 1] = acc[ni][rr * 2 + 1];
        }
    __syncthreads();
    if (tid < 128) {
        int g = tid >> 6, d = tid & 63;
        float s = 0.f;
#pragma unroll 8
        for (int m = 0; m < 64; m++)
            s += Sf[(g * 64 + m) * 65 + d] * linv[g * 64 + m];
        int h = blockIdx.x * 2 + g;
        g_z2[(i * NH + h) * DHH + d] = s;
    }
}

// =============================================================================
// K5: out
// =============================================================================
__global__ __launch_bounds__(256) void final_kernel(float* __restrict__ out)
{
    int g = blockIdx.x * 256 + threadIdx.x;
    int i = g >> 9;
    int rest = g & 511;
    int h = rest >> 6;
    int d = rest & 63;

    const float* zp = &g_z1[((h * NM) * LQ + i) * DHH + d];
    float s = g_z2[(i * NH + h) * DHH + d];
#pragma unroll 8
    for (int m = 0; m < 64; m++) s += zp[m * (LQ * DHH)];
    out[g] = s;
}

// =============================================================================
extern "C" void kernel_launch(void* const* d_in, const int* in_sizes, int n_in,
                              void* d_out, int out_size)
{
    const float* x  = (const float*)d_in[0];
    const float* Wq = (const float*)d_in[1];
    const float* Wk = (const float*)d_in[2];
    const float* Wv = (const float*)d_in[3];
    const float* aK = (const float*)d_in[4];
    const float* aV = (const float*)d_in[5];
    float* out = (float*)d_out;

    cudaFuncSetAttribute(proj_mma_kernel,
                         cudaFuncAttributeMaxDynamicSharedMemorySize, P_TOT);
    cudaFuncSetAttribute(e2_mma_kernel,
                         cudaFuncAttributeMaxDynamicSharedMemorySize, E2_TOT);
    cudaFuncSetAttribute(attn_mma_kernel,
                         cudaFuncAttributeMaxDynamicSharedMemorySize, A3_TOT);
    cudaFuncSetAttribute(z2_mma_kernel,
                         cudaFuncAttributeMaxDynamicSharedMemorySize, Z3_TOT);

    __nv_bfloat16 *xhi_p, *xlo_p, *whi_p, *wlo_p, *akhi_p, *aklo_p, *avhi_p, *avlo_p;
    cudaGetSymbolAddress((void**)&xhi_p,  g_xhi);
    cudaGetSymbolAddress((void**)&xlo_p,  g_xlo);
    cudaGetSymbolAddress((void**)&whi_p,  g_whi);
    cudaGetSymbolAddress((void**)&wlo_p,  g_wlo);
    cudaGetSymbolAddress((void**)&akhi_p, g_akhi);
    cudaGetSymbolAddress((void**)&aklo_p, g_aklo);
    cudaGetSymbolAddress((void**)&avhi_p, g_avhi);
    cudaGetSymbolAddress((void**)&avlo_p, g_avlo);

    SplitArgs sa;
    sa.src[0] = x;  sa.hi[0] = xhi_p;  sa.lo[0] = xlo_p;
    sa.src[1] = Wq; sa.hi[1] = whi_p;  sa.lo[1] = wlo_p;
    sa.src[2] = Wk; sa.hi[2] = whi_p + DMOD * DMOD; sa.lo[2] = wlo_p + DMOD * DMOD;
    sa.src[3] = Wv; sa.hi[3] = whi_p + 2 * DMOD * DMOD; sa.lo[3] = wlo_p + 2 * DMOD * DMOD;
    sa.src[4] = aK; sa.hi[4] = akhi_p; sa.lo[4] = aklo_p;
    sa.src[5] = aV; sa.hi[5] = avhi_p; sa.lo[5] = avlo_p;
    int nv[6] = {NTOK * DMOD / 4, DMOD * DMOD / 4, DMOD * DMOD / 4,
                 DMOD * DMOD / 4, LQ * LQ * DHH / 4, LQ * LQ * DHH / 4};
    sa.off[0] = 0;
    for (int s = 0; s < 6; s++) sa.off[s + 1] = sa.off[s] + nv[s];

    split_all_kernel<<<4096, 256>>>(sa);

    proj_mma_kernel<<<dim3(NTOK / 128, DMOD / 128, 3), 256, P_TOT>>>();
    e2_mma_kernel<<<dim3(4, 2, LQ), 256, E2_TOT>>>();
    attn_mma_kernel<<<dim3(NSL, 2), 256, A3_TOT>>>();
    z2_mma_kernel<<<dim3(4, LQ), 256, Z3_TOT>>>();
    final_kernel<<<512, 256>>>(out);
}

// round 10
// speedup vs baseline: 1.0712x; 1.0712x over previous
#include <cuda_runtime.h>
#include <cuda_bf16.h>
#include <cuda_fp16.h>
#include <cstdint>
#include <math.h>

#define LQ   256
#define DHH  64
#define NH   8
#define NM   64
#define NSL  (NH*NM)   // 512
#define DMOD 512
#define NTOK (NM*LQ)   // 16384

// ---------------- scratch -------------
__device__ float g_e2[LQ * NSL * LQ];        // [i][hm][j]
__device__ float g_z1[NSL * LQ * DHH];       // [hm][i][d]
__device__ float g_z2[LQ * NH * DHH];        // [i][h][d]
__device__ float g_invl[NSL * LQ];           // [hm][i]

__device__ __nv_bfloat16 g_xhi[NTOK * DMOD];
__device__ __nv_bfloat16 g_xlo[NTOK * DMOD];
__device__ __nv_bfloat16 g_whi[3 * DMOD * DMOD];
__device__ __nv_bfloat16 g_wlo[3 * DMOD * DMOD];
__device__ __nv_bfloat16 g_qhi[NSL * LQ * DHH];
__device__ __nv_bfloat16 g_qlo[NSL * LQ * DHH];
__device__ __nv_bfloat16 g_khi[NSL * LQ * DHH];
__device__ __nv_bfloat16 g_klo[NSL * LQ * DHH];
__device__ __nv_bfloat16 g_vhi[NSL * LQ * DHH];
__device__ __nv_bfloat16 g_vlo[NSL * LQ * DHH];
__device__ __nv_bfloat16 g_akhi[LQ * LQ * DHH];
__device__ __nv_bfloat16 g_aklo[LQ * LQ * DHH];
__device__ __half g_avhi16[LQ * LQ * DHH];
__device__ __half g_avlo16[LQ * LQ * DHH];
__device__ __half g_a16[LQ * NSL * LQ];      // unnormalized p, fp16 [i][hm][j]

// ========================= helpers ==================================
__device__ __forceinline__ uint32_t smem_to_u32(const void* p) {
    uint32_t a;
    asm("{ .reg .u64 t; cvta.to.shared.u64 t, %1; cvt.u32.u64 %0, t; }"
        : "=r"(a) : "l"(p));
    return a;
}
__device__ __forceinline__ void ldsm_x4(uint32_t addr, uint32_t* r) {
    asm volatile("ldmatrix.sync.aligned.m8n8.x4.shared.b16 {%0,%1,%2,%3}, [%4];"
        : "=r"(r[0]), "=r"(r[1]), "=r"(r[2]), "=r"(r[3]) : "r"(addr));
}
__device__ __forceinline__ void ldsm_x4_t(uint32_t addr, uint32_t* r) {
    asm volatile("ldmatrix.sync.aligned.m8n8.x4.trans.shared.b16 {%0,%1,%2,%3}, [%4];"
        : "=r"(r[0]), "=r"(r[1]), "=r"(r[2]), "=r"(r[3]) : "r"(addr));
}
__device__ __forceinline__ void mma_bf16(float* c, const uint32_t* a,
                                         const uint32_t* b) {
    asm volatile(
        "mma.sync.aligned.m16n8k16.row.col.f32.bf16.bf16.f32 "
        "{%0,%1,%2,%3}, {%4,%5,%6,%7}, {%8,%9}, {%0,%1,%2,%3};"
        : "+f"(c[0]), "+f"(c[1]), "+f"(c[2]), "+f"(c[3])
        : "r"(a[0]), "r"(a[1]), "r"(a[2]), "r"(a[3]), "r"(b[0]), "r"(b[1]));
}
__device__ __forceinline__ void mma_f16(float* c, const uint32_t* a,
                                        const uint32_t* b) {
    asm volatile(
        "mma.sync.aligned.m16n8k16.row.col.f32.f16.f16.f32 "
        "{%0,%1,%2,%3}, {%4,%5,%6,%7}, {%8,%9}, {%0,%1,%2,%3};"
        : "+f"(c[0]), "+f"(c[1]), "+f"(c[2]), "+f"(c[3])
        : "r"(a[0]), "r"(a[1]), "r"(a[2]), "r"(a[3]), "r"(b[0]), "r"(b[1]));
}
__device__ __forceinline__ uint32_t pack_bf16(float a, float b) {
    __nv_bfloat162 h(__float2bfloat16(a), __float2bfloat16(b));
    return *(uint32_t*)&h;
}
__device__ __forceinline__ uint32_t pack_f16(float a, float b) {
    __half2 h(__float2half(a), __float2half(b));
    return *(uint32_t*)&h;
}
__device__ __forceinline__ void cp16(uint32_t s, const void* g) {
    asm volatile("cp.async.cg.shared.global [%0], [%1], 16;"
                 :: "r"(s), "l"(g) : "memory");
}
#define CP_COMMIT() asm volatile("cp.async.commit_group;" ::: "memory")
#define CP_WAIT(n)  asm volatile("cp.async.wait_group %0;" :: "n"(n) : "memory")

// ============================================================================
// merged split: segs 0-4 -> bf16 hi/lo, seg 5 (aV) -> fp16 hi/lo
// ============================================================================
struct SplitArgs {
    const float* src[6];
    void* hi[6];
    void* lo[6];
    int off[7];
};

__global__ __launch_bounds__(256) void split_all_kernel(SplitArgs a)
{
    int total = a.off[6];
    for (int idx = blockIdx.x * 256 + threadIdx.x; idx < total;
         idx += gridDim.x * 256) {
        int seg = 0;
#pragma unroll
        for (int s = 1; s < 6; s++) if (idx >= a.off[s]) seg = s;
        int li = idx - a.off[seg];
        float4 v = *(const float4*)&a.src[seg][li * 4];
        if (seg == 5) {
            __half h0 = __float2half(v.x);
            __half h1 = __float2half(v.y);
            __half h2 = __float2half(v.z);
            __half h3 = __float2half(v.w);
            __half2 hp0(h0, h1), hp1(h2, h3);
            __half2 lp0(__float2half(v.x - __half2float(h0)),
                        __float2half(v.y - __half2float(h1)));
            __half2 lp1(__float2half(v.z - __half2float(h2)),
                        __float2half(v.w - __half2float(h3)));
            __half* hp = (__half*)a.hi[5];
            __half* lp = (__half*)a.lo[5];
            *(__half2*)&hp[li * 4]     = hp0;
            *(__half2*)&hp[li * 4 + 2] = hp1;
            *(__half2*)&lp[li * 4]     = lp0;
            *(__half2*)&lp[li * 4 + 2] = lp1;
        } else {
            __nv_bfloat16 h0 = __float2bfloat16(v.x);
            __nv_bfloat16 h1 = __float2bfloat16(v.y);
            __nv_bfloat16 h2 = __float2bfloat16(v.z);
            __nv_bfloat16 h3 = __float2bfloat16(v.w);
            __nv_bfloat162 hp0(h0, h1), hp1(h2, h3);
            __nv_bfloat162 lp0(__float2bfloat16(v.x - __bfloat162float(h0)),
                               __float2bfloat16(v.y - __bfloat162float(h1)));
            __nv_bfloat162 lp1(__float2bfloat16(v.z - __bfloat162float(h2)),
                               __float2bfloat16(v.w - __bfloat162float(h3)));
            __nv_bfloat16* hp = (__nv_bfloat16*)a.hi[seg];
            __nv_bfloat16* lp = (__nv_bfloat16*)a.lo[seg];
            *(__nv_bfloat162*)&hp[li * 4]     = hp0;
            *(__nv_bfloat162*)&hp[li * 4 + 2] = hp1;
            *(__nv_bfloat162*)&lp[li * 4]     = lp0;
            *(__nv_bfloat162*)&lp[li * 4 + 2] = lp1;
        }
    }
}

// ============================================================================
// K1: projection GEMM (unchanged)
// ============================================================================
#define PMAT  (128 * 80)
#define PSTG  (4 * PMAT)
#define P_TOT (2 * PSTG)      // 81920

__global__ __launch_bounds__(256) void proj_mma_kernel()
{
    extern __shared__ __align__(16) unsigned char dsm[];
    const uint32_t sb = smem_to_u32(dsm);

    const int tid = threadIdx.x, lane = tid & 31, wid = tid >> 5;
    const int t0 = blockIdx.x * 128;
    const int n0 = blockIdx.y * 128;
    const int sel = blockIdx.z;

    const __nv_bfloat16* Ah = g_xhi;
    const __nv_bfloat16* Al = g_xlo;
    const __nv_bfloat16* Bh = g_whi + sel * DMOD * DMOD;
    const __nv_bfloat16* Bl = g_wlo + sel * DMOD * DMOD;
    __nv_bfloat16 *hip, *lop;
    if (sel == 0)      { hip = g_qhi; lop = g_qlo; }
    else if (sel == 1) { hip = g_khi; lop = g_klo; }
    else               { hip = g_vhi; lop = g_vlo; }

    const int wm = (wid & 3) * 32;
    const int wn = (wid >> 2) * 64;
    const int lr  = (tid >> 2);
    const int seg = tid & 3;

    auto stage_load = [&](int ch, int st) {
        const int k0 = ch * 32;
        uint32_t s0 = sb + st * PSTG;
#pragma unroll
        for (int l = 0; l < 8; l++) {
            int mat = l >> 1;
            int r = (l & 1) * 64 + lr;
            const __nv_bfloat16* gp;
            int row;
            if (mat == 0)      { gp = Ah; row = t0 + r; }
            else if (mat == 1) { gp = Al; row = t0 + r; }
            else if (mat == 2) { gp = Bh; row = n0 + r; }
            else               { gp = Bl; row = n0 + r; }
            cp16(s0 + mat * PMAT + r * 80 + seg * 16,
                 &gp[row * DMOD + k0 + seg * 8]);
        }
    };

    float acc[2][8][4];
#pragma unroll
    for (int a = 0; a < 2; a++)
#pragma unroll
        for (int b = 0; b < 8; b++)
#pragma unroll
            for (int c = 0; c < 4; c++) acc[a][b][c] = 0.f;

    stage_load(0, 0);
    CP_COMMIT();

    for (int ch = 0; ch < 16; ch++) {
        const int st = ch & 1;
        if (ch + 1 < 16) { stage_load(ch + 1, st ^ 1); CP_COMMIT(); CP_WAIT(1); }
        else             { CP_WAIT(0); }
        __syncthreads();

        const uint32_t s0 = sb + st * PSTG;
#pragma unroll
        for (int s = 0; s < 2; s++) {
            uint32_t ah[2][4], al[2][4];
#pragma unroll
            for (int mi = 0; mi < 2; mi++) {
                int row = wm + mi * 16 + (lane & 15);
                uint32_t ad = s0 + row * 80 + s * 32 + ((lane >> 4) & 1) * 16;
                ldsm_x4(ad, ah[mi]);
                ldsm_x4(ad + PMAT, al[mi]);
            }
#pragma unroll
            for (int p = 0; p < 4; p++) {
                uint32_t bh[4], bl[4];
                int row = wn + p * 16 + (lane & 7) + ((lane >> 4) & 1) * 8;
                uint32_t bd = s0 + 2 * PMAT + row * 80 + s * 32 + ((lane >> 3) & 1) * 16;
                ldsm_x4(bd, bh);
                ldsm_x4(bd + PMAT, bl);
#pragma unroll
                for (int mi = 0; mi < 2; mi++)
#pragma unroll
                    for (int su = 0; su < 2; su++) {
                        mma_bf16(acc[mi][p * 2 + su], ah[mi], &bh[su * 2]);
                        mma_bf16(acc[mi][p * 2 + su], ah[mi], &bl[su * 2]);
                        mma_bf16(acc[mi][p * 2 + su], al[mi], &bh[su * 2]);
                    }
            }
        }
        __syncthreads();
    }

#pragma unroll
    for (int mi = 0; mi < 2; mi++)
#pragma unroll
        for (int ni = 0; ni < 8; ni++) {
            int e = n0 + wn + ni * 8 + (lane & 3) * 2;
            int h = e >> 6, d = e & 63;
#pragma unroll
            for (int rr = 0; rr < 2; rr++) {
                int t = t0 + wm + mi * 16 + (lane >> 2) + rr * 8;
                int m = t >> 8, i = t & 255;
                int idx = ((h * NM + m) * LQ + i) * DHH + d;
                float vx = acc[mi][ni][rr * 2 + 0];
                float vy = acc[mi][ni][rr * 2 + 1];
                __nv_bfloat16 h0 = __float2bfloat16(vx);
                __nv_bfloat16 h1 = __float2bfloat16(vy);
                __nv_bfloat162 hp(h0, h1);
                __nv_bfloat162 lp(__float2bfloat16(vx - __bfloat162float(h0)),
                                  __float2bfloat16(vy - __bfloat162float(h1)));
                *(__nv_bfloat162*)&hip[idx] = hp;
                *(__nv_bfloat162*)&lop[idx] = lp;
            }
        }
}

// ============================================================================
// K2: e2 (unchanged)
// ============================================================================
#define E2_AHI 0
#define E2_ASZ (128 * 144)
#define E2_B   (2 * E2_ASZ)
#define E2_TOT (4 * E2_ASZ)

__global__ __launch_bounds__(256) void e2_mma_kernel()
{
    extern __shared__ __align__(16) unsigned char dsm[];
    const uint32_t sb = smem_to_u32(dsm);

    const int tid = threadIdx.x, lane = tid & 31, wid = tid >> 5;
    const int hm0 = blockIdx.x * 128;
    const int j0  = blockIdx.y * 128;
    const int i   = blockIdx.z;
    const int wm = (wid & 3) * 32;
    const int wn = (wid >> 2) * 64;

#pragma unroll
    for (int l = 0; l < 4; l++) {
        int id = tid + l * 256;
        int r = id >> 3, c = id & 7;
        int ga = ((hm0 + r) * LQ + i) * DHH + c * 8;
        cp16(sb + E2_AHI + r * 144 + c * 16, &g_qhi[ga]);
        cp16(sb + E2_AHI + E2_ASZ + r * 144 + c * 16, &g_qlo[ga]);
        int gb = (i * LQ + j0 + r) * DHH + c * 8;
        cp16(sb + E2_B + r * 144 + c * 16, &g_akhi[gb]);
        cp16(sb + E2_B + E2_ASZ + r * 144 + c * 16, &g_aklo[gb]);
    }
    CP_COMMIT();
    CP_WAIT(0);
    __syncthreads();

    float acc[2][8][4];
#pragma unroll
    for (int a = 0; a < 2; a++)
#pragma unroll
        for (int b = 0; b < 8; b++)
#pragma unroll
            for (int c = 0; c < 4; c++) acc[a][b][c] = 0.f;

#pragma unroll
    for (int s = 0; s < 4; s++) {
        uint32_t ah[2][4], al[2][4];
#pragma unroll
        for (int mi = 0; mi < 2; mi++) {
            uint32_t ad = sb + E2_AHI + (wm + mi * 16 + (lane & 15)) * 144 +
                          s * 32 + ((lane >> 4) & 1) * 16;
            ldsm_x4(ad, ah[mi]);
            ldsm_x4(ad + E2_ASZ, al[mi]);
        }
#pragma unroll
        for (int p = 0; p < 4; p++) {
            uint32_t bh[4], bl[4];
            uint32_t bd = sb + E2_B + (wn + p * 16 + (lane & 7) + ((lane >> 4) & 1) * 8) * 144 +
                          s * 32 + ((lane >> 3) & 1) * 16;
            ldsm_x4(bd, bh);
            ldsm_x4(bd + E2_ASZ, bl);
#pragma unroll
            for (int mi = 0; mi < 2; mi++)
#pragma unroll
                for (int su = 0; su < 2; su++) {
                    mma_bf16(acc[mi][p * 2 + su], ah[mi], &bh[su * 2]);
                    mma_bf16(acc[mi][p * 2 + su], ah[mi], &bl[su * 2]);
                    mma_bf16(acc[mi][p * 2 + su], al[mi], &bh[su * 2]);
                }
        }
    }

#pragma unroll
    for (int mi = 0; mi < 2; mi++)
#pragma unroll
        for (int ni = 0; ni < 8; ni++) {
            int j = j0 + wn + ni * 8 + (lane & 3) * 2;
#pragma unroll
            for (int rr = 0; rr < 2; rr++) {
                int hm = hm0 + wm + mi * 16 + (lane >> 2) + rr * 8;
                *(float2*)&g_e2[(i * NSL + hm) * LQ + j] =
                    make_float2(acc[mi][ni][rr * 2 + 0], acc[mi][ni][rr * 2 + 1]);
            }
        }
}

// ============================================================================
// K3: fused attention; grid (i-half, hm) — same-hm halves adjacent for L2.
// p stored to global as single fp16 (z2 operand); z1 keeps bf16 hi/lo in regs.
// ============================================================================
#define A3_KSZ  (64 * 144)           // 9216
#define A3_STG  (4 * A3_KSZ)         // 36864
#define A3_Q    (2 * A3_STG)         // 73728
#define A3_QSZ  (128 * 144)          // 18432
#define A3_TOT  (A3_Q + 2 * A3_QSZ)  // 110592

__global__ __launch_bounds__(256) void attn_mma_kernel()
{
    extern __shared__ __align__(16) unsigned char dsm[];
    const uint32_t sb = smem_to_u32(dsm);
    const int tid = threadIdx.x, lane = tid & 31, wid = tid >> 5;
    const int i0 = blockIdx.x * 128;
    const int hm = blockIdx.y;
    const int wm = wid * 16;
    const int gr = lane >> 2, qd = lane & 3;

    auto load_kv = [&](int jc, int st) {
        uint32_t s0 = sb + st * A3_STG;
#pragma unroll
        for (int l = 0; l < 2; l++) {
            int id = tid + l * 256;
            int r = id >> 3, c = id & 7;
            int gk = (hm * LQ + jc * 64 + r) * DHH + c * 8;
            cp16(s0 + 0 * A3_KSZ + r * 144 + c * 16, &g_khi[gk]);
            cp16(s0 + 1 * A3_KSZ + r * 144 + c * 16, &g_klo[gk]);
            cp16(s0 + 2 * A3_KSZ + r * 144 + c * 16, &g_vhi[gk]);
            cp16(s0 + 3 * A3_KSZ + r * 144 + c * 16, &g_vlo[gk]);
        }
    };

    // Q resident (128 rows)
#pragma unroll
    for (int l = 0; l < 4; l++) {
        int id = tid + l * 256;
        int r = id >> 3, c = id & 7;
        int gq = (hm * LQ + i0 + r) * DHH + c * 8;
        cp16(sb + A3_Q + r * 144 + c * 16, &g_qhi[gq]);
        cp16(sb + A3_Q + A3_QSZ + r * 144 + c * 16, &g_qlo[gq]);
    }
    CP_COMMIT();
    load_kv(0, 0);
    CP_COMMIT();

    float accz[8][4];
#pragma unroll
    for (int b = 0; b < 8; b++)
#pragma unroll
        for (int c = 0; c < 4; c++) accz[b][c] = 0.f;
    float rsum[2] = {0.f, 0.f};

    for (int jc = 0; jc < 4; jc++) {
        const int st = jc & 1;
        __syncthreads();
        if (jc < 3) { load_kv(jc + 1, st ^ 1); CP_COMMIT(); CP_WAIT(1); }
        else        { CP_WAIT(0); }
        __syncthreads();

        const uint32_t s0 = sb + st * A3_STG;

        // ---- scores: e1 = q k^T ----
        float acc[8][4];
#pragma unroll
        for (int b = 0; b < 8; b++)
#pragma unroll
            for (int c = 0; c < 4; c++) acc[b][c] = 0.f;

#pragma unroll
        for (int s = 0; s < 4; s++) {
            uint32_t ah[4], al[4];
            uint32_t ad = sb + A3_Q + (wm + (lane & 15)) * 144 +
                          s * 32 + ((lane >> 4) & 1) * 16;
            ldsm_x4(ad, ah);
            ldsm_x4(ad + A3_QSZ, al);
#pragma unroll
            for (int p = 0; p < 4; p++) {
                uint32_t bh[4], bl[4];
                uint32_t bd = s0 + (p * 16 + (lane & 7) + ((lane >> 4) & 1) * 8) * 144 +
                              s * 32 + ((lane >> 3) & 1) * 16;
                ldsm_x4(bd, bh);
                ldsm_x4(bd + A3_KSZ, bl);
#pragma unroll
                for (int su = 0; su < 2; su++) {
                    mma_bf16(acc[p * 2 + su], ah, &bh[su * 2]);
                    mma_bf16(acc[p * 2 + su], ah, &bl[su * 2]);
                    mma_bf16(acc[p * 2 + su], al, &bh[su * 2]);
                }
            }
        }

        // ---- + e2, scale, exp, rowsum, pack p ----
        uint32_t phh[8][2], pll[8][2];
        {
            int ir0 = i0 + wm + gr;
            float2 e2b0[8], e2b1[8];
#pragma unroll
            for (int ni = 0; ni < 8; ni++) {
                int col = jc * 64 + ni * 8 + qd * 2;
                e2b0[ni] = *(const float2*)&g_e2[(ir0 * NSL + hm) * LQ + col];
                e2b1[ni] = *(const float2*)&g_e2[((ir0 + 8) * NSL + hm) * LQ + col];
            }
#pragma unroll
            for (int ni = 0; ni < 8; ni++) {
                int col = jc * 64 + ni * 8 + qd * 2;
                float e0 = __expf((acc[ni][0] + e2b0[ni].x) * 0.125f);
                float e1 = __expf((acc[ni][1] + e2b0[ni].y) * 0.125f);
                float e2v = __expf((acc[ni][2] + e2b1[ni].x) * 0.125f);
                float e3 = __expf((acc[ni][3] + e2b1[ni].y) * 0.125f);
                rsum[0] += e0 + e1;
                rsum[1] += e2v + e3;
                // bf16 hi/lo for in-register z1 A-operand
                uint32_t h01 = pack_bf16(e0, e1);
                uint32_t h23 = pack_bf16(e2v, e3);
                __nv_bfloat162 hh01 = *(__nv_bfloat162*)&h01;
                __nv_bfloat162 hh23 = *(__nv_bfloat162*)&h23;
                uint32_t l01 = pack_bf16(e0 - __bfloat162float(hh01.x),
                                         e1 - __bfloat162float(hh01.y));
                uint32_t l23 = pack_bf16(e2v - __bfloat162float(hh23.x),
                                         e3 - __bfloat162float(hh23.y));
                phh[ni][0] = h01; phh[ni][1] = h23;
                pll[ni][0] = l01; pll[ni][1] = l23;
                // fp16 single for z2 (global)
                *(uint32_t*)&g_a16[(ir0 * NSL + hm) * LQ + col] = pack_f16(e0, e1);
                *(uint32_t*)&g_a16[((ir0 + 8) * NSL + hm) * LQ + col] = pack_f16(e2v, e3);
            }
        }

        // ---- z1 += p V ----
#pragma unroll
        for (int s = 0; s < 4; s++) {
            uint32_t Ahf[4] = {phh[2 * s][0], phh[2 * s][1],
                               phh[2 * s + 1][0], phh[2 * s + 1][1]};
            uint32_t Alf[4] = {pll[2 * s][0], pll[2 * s][1],
                               pll[2 * s + 1][0], pll[2 * s + 1][1]};
#pragma unroll
            for (int p = 0; p < 4; p++) {
                uint32_t bh[4], bl[4];
                uint32_t bd = s0 + 2 * A3_KSZ + (s * 16 + (lane & 15)) * 144 +
                              p * 32 + ((lane >> 4) & 1) * 16;
                ldsm_x4_t(bd, bh);
                ldsm_x4_t(bd + A3_KSZ, bl);
#pragma unroll
                for (int su = 0; su < 2; su++) {
                    mma_bf16(accz[p * 2 + su], Ahf, &bh[su * 2]);
                    mma_bf16(accz[p * 2 + su], Ahf, &bl[su * 2]);
                    mma_bf16(accz[p * 2 + su], Alf, &bh[su * 2]);
                }
            }
        }
    }

    // ---- finalize ----
    float inv[2];
#pragma unroll
    for (int rr = 0; rr < 2; rr++) {
        float r = rsum[rr];
        r += __shfl_xor_sync(0xffffffffu, r, 1);
        r += __shfl_xor_sync(0xffffffffu, r, 2);
        inv[rr] = 1.f / r;
    }
    if (qd == 0) {
#pragma unroll
        for (int rr = 0; rr < 2; rr++)
            g_invl[hm * LQ + i0 + wm + gr + rr * 8] = inv[rr];
    }
#pragma unroll
    for (int ni = 0; ni < 8; ni++)
#pragma unroll
        for (int rr = 0; rr < 2; rr++) {
            int ir = i0 + wm + gr + rr * 8;
            int d = ni * 8 + qd * 2;
            *(float2*)&g_z1[(hm * LQ + ir) * DHH + d] =
                make_float2(accz[ni][rr * 2 + 0] * inv[rr],
                            accz[ni][rr * 2 + 1] * inv[rr]);
        }
}

// ============================================================================
// K4: z2 GEMM in fp16: A = p (single fp16), B = aV fp16 hi/lo -> 2 passes.
// grid (4 hm-quarters, i). CTA = 128 rows, warp = 16 rows.
// ============================================================================
#define Z4_ASZ  (128 * 144)                  // 18432 (fp16 A)
#define Z4_KVSZ (64 * 144)                   // 9216
#define Z4_STG  (Z4_ASZ + 2 * Z4_KVSZ)       // 36864
#define Z4_LINV (2 * Z4_STG)                 // 73728
#define Z4_TOT  (Z4_LINV + 512)              // 74240

__global__ __launch_bounds__(256) void z2_mma_kernel()
{
    extern __shared__ __align__(16) unsigned char dsm[];
    const uint32_t sb = smem_to_u32(dsm);
    const int tid = threadIdx.x, lane = tid & 31, wid = tid >> 5;
    const int hm0 = blockIdx.x * 128;
    const int i = blockIdx.y;
    const int wm = wid * 16;
    float* linv = (float*)(dsm + Z4_LINV);

    if (tid < 128) linv[tid] = g_invl[(hm0 + tid) * LQ + i];

    auto load_chunk = [&](int jc, int st) {
        uint32_t s0 = sb + st * Z4_STG;
#pragma unroll
        for (int l = 0; l < 4; l++) {
            int id = tid + l * 256;
            int r = id >> 3, c = id & 7;
            int ga = (i * NSL + hm0 + r) * LQ + jc * 64 + c * 8;
            cp16(s0 + r * 144 + c * 16, &g_a16[ga]);
        }
#pragma unroll
        for (int l = 0; l < 2; l++) {
            int id = tid + l * 256;
            int r = id >> 3, c = id & 7;
            int gb = (i * LQ + jc * 64 + r) * DHH + c * 8;
            cp16(s0 + Z4_ASZ + r * 144 + c * 16, &g_avhi16[gb]);
            cp16(s0 + Z4_ASZ + Z4_KVSZ + r * 144 + c * 16, &g_avlo16[gb]);
        }
    };

    load_chunk(0, 0);
    CP_COMMIT();

    float acc[8][4];
#pragma unroll
    for (int b = 0; b < 8; b++)
#pragma unroll
        for (int c = 0; c < 4; c++) acc[b][c] = 0.f;

    for (int jc = 0; jc < 4; jc++) {
        const int st = jc & 1;
        __syncthreads();
        if (jc < 3) { load_chunk(jc + 1, st ^ 1); CP_COMMIT(); CP_WAIT(1); }
        else        { CP_WAIT(0); }
        __syncthreads();

        const uint32_t s0 = sb + st * Z4_STG;
#pragma unroll
        for (int s = 0; s < 4; s++) {
            uint32_t af[4];
            uint32_t ad = s0 + (wm + (lane & 15)) * 144 +
                          s * 32 + ((lane >> 4) & 1) * 16;
            ldsm_x4(ad, af);
#pragma unroll
            for (int p = 0; p < 4; p++) {
                uint32_t bh[4], bl[4];
                uint32_t bd = s0 + Z4_ASZ + (s * 16 + (lane & 15)) * 144 +
                              p * 32 + ((lane >> 4) & 1) * 16;
                ldsm_x4_t(bd, bh);
                ldsm_x4_t(bd + Z4_KVSZ, bl);
#pragma unroll
                for (int su = 0; su < 2; su++) {
                    mma_f16(acc[p * 2 + su], af, &bh[su * 2]);
                    mma_f16(acc[p * 2 + su], af, &bl[su * 2]);
                }
            }
        }
    }

    // reduce over m (2 h-groups of 64) with invl scaling
    __syncthreads();
    float* Sf = (float*)dsm;   // [128][65]
#pragma unroll
    for (int ni = 0; ni < 8; ni++)
#pragma unroll
        for (int rr = 0; rr < 2; rr++) {
            int r = wm + (lane >> 2) + rr * 8;
            int c = ni * 8 + (lane & 3) * 2;
            Sf[r * 65 + c]     = acc[ni][rr * 2 + 0];
            Sf[r * 65 + c + 1] = acc[ni][rr * 2 + 1];
        }
    __syncthreads();
    if (tid < 128) {
        int g = tid >> 6, d = tid & 63;
        float s = 0.f;
#pragma unroll 8
        for (int m = 0; m < 64; m++)
            s += Sf[(g * 64 + m) * 65 + d] * linv[g * 64 + m];
        int h = blockIdx.x * 2 + g;
        g_z2[(i * NH + h) * DHH + d] = s;
    }
}

// =============================================================================
// K5: out
// =============================================================================
__global__ __launch_bounds__(256) void final_kernel(float* __restrict__ out)
{
    int g = blockIdx.x * 256 + threadIdx.x;
    int i = g >> 9;
    int rest = g & 511;
    int h = rest >> 6;
    int d = rest & 63;

    const float* zp = &g_z1[((h * NM) * LQ + i) * DHH + d];
    float s = g_z2[(i * NH + h) * DHH + d];
#pragma unroll 8
    for (int m = 0; m < 64; m++) s += zp[m * (LQ * DHH)];
    out[g] = s;
}

// =============================================================================
extern "C" void kernel_launch(void* const* d_in, const int* in_sizes, int n_in,
                              void* d_out, int out_size)
{
    const float* x  = (const float*)d_in[0];
    const float* Wq = (const float*)d_in[1];
    const float* Wk = (const float*)d_in[2];
    const float* Wv = (const float*)d_in[3];
    const float* aK = (const float*)d_in[4];
    const float* aV = (const float*)d_in[5];
    float* out = (float*)d_out;

    cudaFuncSetAttribute(proj_mma_kernel,
                         cudaFuncAttributeMaxDynamicSharedMemorySize, P_TOT);
    cudaFuncSetAttribute(e2_mma_kernel,
                         cudaFuncAttributeMaxDynamicSharedMemorySize, E2_TOT);
    cudaFuncSetAttribute(attn_mma_kernel,
                         cudaFuncAttributeMaxDynamicSharedMemorySize, A3_TOT);
    cudaFuncSetAttribute(z2_mma_kernel,
                         cudaFuncAttributeMaxDynamicSharedMemorySize, Z4_TOT);

    void *xhi_p, *xlo_p, *whi_p, *wlo_p, *akhi_p, *aklo_p, *avhi_p, *avlo_p;
    cudaGetSymbolAddress(&xhi_p,  g_xhi);
    cudaGetSymbolAddress(&xlo_p,  g_xlo);
    cudaGetSymbolAddress(&whi_p,  g_whi);
    cudaGetSymbolAddress(&wlo_p,  g_wlo);
    cudaGetSymbolAddress(&akhi_p, g_akhi);
    cudaGetSymbolAddress(&aklo_p, g_aklo);
    cudaGetSymbolAddress(&avhi_p, g_avhi16);
    cudaGetSymbolAddress(&avlo_p, g_avlo16);

    SplitArgs sa;
    sa.src[0] = x;  sa.hi[0] = xhi_p;  sa.lo[0] = xlo_p;
    sa.src[1] = Wq; sa.hi[1] = whi_p;  sa.lo[1] = wlo_p;
    sa.src[2] = Wk; sa.hi[2] = (__nv_bfloat16*)whi_p + DMOD * DMOD;
                    sa.lo[2] = (__nv_bfloat16*)wlo_p + DMOD * DMOD;
    sa.src[3] = Wv; sa.hi[3] = (__nv_bfloat16*)whi_p + 2 * DMOD * DMOD;
                    sa.lo[3] = (__nv_bfloat16*)wlo_p + 2 * DMOD * DMOD;
    sa.src[4] = aK; sa.hi[4] = akhi_p; sa.lo[4] = aklo_p;
    sa.src[5] = aV; sa.hi[5] = avhi_p; sa.lo[5] = avlo_p;
    int nv[6] = {NTOK * DMOD / 4, DMOD * DMOD / 4, DMOD * DMOD / 4,
                 DMOD * DMOD / 4, LQ * LQ * DHH / 4, LQ * LQ * DHH / 4};
    sa.off[0] = 0;
    for (int s = 0; s < 6; s++) sa.off[s + 1] = sa.off[s] + nv[s];

    split_all_kernel<<<4096, 256>>>(sa);

    proj_mma_kernel<<<dim3(NTOK / 128, DMOD / 128, 3), 256, P_TOT>>>();
    e2_mma_kernel<<<dim3(4, 2, LQ), 256, E2_TOT>>>();
    attn_mma_kernel<<<dim3(2, NSL), 256, A3_TOT>>>();
    z2_mma_kernel<<<dim3(4, LQ), 256, Z4_TOT>>>();
    final_kernel<<<512, 256>>>(out);
}

// round 11
// speedup vs baseline: 1.3792x; 1.2875x over previous
#include <cuda_runtime.h>
#include <cuda_bf16.h>
#include <cuda_fp16.h>
#include <cstdint>
#include <math.h>

#define LQ   256
#define DHH  64
#define NH   8
#define NM   64
#define NSL  (NH*NM)   // 512
#define DMOD 512
#define NTOK (NM*LQ)   // 16384

// ---------------- scratch -------------
__device__ float g_e2[LQ * NSL * LQ];        // [i][hm][j]
__device__ float g_z1[NSL * LQ * DHH];       // [hm][i][d]
__device__ float g_z2[LQ * NH * DHH];        // [i][h][d]
__device__ float g_invl[NSL * LQ];           // [hm][i]

__device__ __nv_bfloat16 g_xhi[NTOK * DMOD];
__device__ __nv_bfloat16 g_xlo[NTOK * DMOD];
__device__ __nv_bfloat16 g_whi[3 * DMOD * DMOD];
__device__ __nv_bfloat16 g_wlo[3 * DMOD * DMOD];
__device__ __half g_q16[NSL * LQ * DHH];     // [hm][i][d]
__device__ __half g_k16[NSL * LQ * DHH];
__device__ __half g_v16[NSL * LQ * DHH];
__device__ __half g_ak16[LQ * LQ * DHH];     // [i][j][d]
__device__ __half g_av16[LQ * LQ * DHH];
__device__ __half g_a16[LQ * NSL * LQ];      // unnormalized p fp16 [i][hm][j]

// ========================= helpers ==================================
__device__ __forceinline__ uint32_t smem_to_u32(const void* p) {
    uint32_t a;
    asm("{ .reg .u64 t; cvta.to.shared.u64 t, %1; cvt.u32.u64 %0, t; }"
        : "=r"(a) : "l"(p));
    return a;
}
__device__ __forceinline__ void ldsm_x4(uint32_t addr, uint32_t* r) {
    asm volatile("ldmatrix.sync.aligned.m8n8.x4.shared.b16 {%0,%1,%2,%3}, [%4];"
        : "=r"(r[0]), "=r"(r[1]), "=r"(r[2]), "=r"(r[3]) : "r"(addr));
}
__device__ __forceinline__ void ldsm_x4_t(uint32_t addr, uint32_t* r) {
    asm volatile("ldmatrix.sync.aligned.m8n8.x4.trans.shared.b16 {%0,%1,%2,%3}, [%4];"
        : "=r"(r[0]), "=r"(r[1]), "=r"(r[2]), "=r"(r[3]) : "r"(addr));
}
__device__ __forceinline__ void mma_bf16(float* c, const uint32_t* a,
                                         const uint32_t* b) {
    asm volatile(
        "mma.sync.aligned.m16n8k16.row.col.f32.bf16.bf16.f32 "
        "{%0,%1,%2,%3}, {%4,%5,%6,%7}, {%8,%9}, {%0,%1,%2,%3};"
        : "+f"(c[0]), "+f"(c[1]), "+f"(c[2]), "+f"(c[3])
        : "r"(a[0]), "r"(a[1]), "r"(a[2]), "r"(a[3]), "r"(b[0]), "r"(b[1]));
}
__device__ __forceinline__ void mma_f16(float* c, const uint32_t* a,
                                        const uint32_t* b) {
    asm volatile(
        "mma.sync.aligned.m16n8k16.row.col.f32.f16.f16.f32 "
        "{%0,%1,%2,%3}, {%4,%5,%6,%7}, {%8,%9}, {%0,%1,%2,%3};"
        : "+f"(c[0]), "+f"(c[1]), "+f"(c[2]), "+f"(c[3])
        : "r"(a[0]), "r"(a[1]), "r"(a[2]), "r"(a[3]), "r"(b[0]), "r"(b[1]));
}
__device__ __forceinline__ uint32_t pack_f16(float a, float b) {
    __half2 h(__float2half(a), __float2half(b));
    return *(uint32_t*)&h;
}
__device__ __forceinline__ void cp16(uint32_t s, const void* g) {
    asm volatile("cp.async.cg.shared.global [%0], [%1], 16;"
                 :: "r"(s), "l"(g) : "memory");
}
#define CP_COMMIT() asm volatile("cp.async.commit_group;" ::: "memory")
#define CP_WAIT(n)  asm volatile("cp.async.wait_group %0;" :: "n"(n) : "memory")

// ============================================================================
// merged split: segs 0-3 (x, W) -> bf16 hi/lo; segs 4-5 (aK, aV) -> fp16
// ============================================================================
struct SplitArgs {
    const float* src[6];
    void* hi[6];
    void* lo[6];
    int off[7];
};

__global__ __launch_bounds__(256) void split_all_kernel(SplitArgs a)
{
    int total = a.off[6];
    for (int idx = blockIdx.x * 256 + threadIdx.x; idx < total;
         idx += gridDim.x * 256) {
        int seg = 0;
#pragma unroll
        for (int s = 1; s < 6; s++) if (idx >= a.off[s]) seg = s;
        int li = idx - a.off[seg];
        float4 v = *(const float4*)&a.src[seg][li * 4];
        if (seg >= 4) {
            __half2 a01(__float2half(v.x), __float2half(v.y));
            __half2 a23(__float2half(v.z), __float2half(v.w));
            __half* hp = (__half*)a.hi[seg];
            *(__half2*)&hp[li * 4]     = a01;
            *(__half2*)&hp[li * 4 + 2] = a23;
        } else {
            __nv_bfloat16 h0 = __float2bfloat16(v.x);
            __nv_bfloat16 h1 = __float2bfloat16(v.y);
            __nv_bfloat16 h2 = __float2bfloat16(v.z);
            __nv_bfloat16 h3 = __float2bfloat16(v.w);
            __nv_bfloat162 hp0(h0, h1), hp1(h2, h3);
            __nv_bfloat162 lp0(__float2bfloat16(v.x - __bfloat162float(h0)),
                               __float2bfloat16(v.y - __bfloat162float(h1)));
            __nv_bfloat162 lp1(__float2bfloat16(v.z - __bfloat162float(h2)),
                               __float2bfloat16(v.w - __bfloat162float(h3)));
            __nv_bfloat16* hp = (__nv_bfloat16*)a.hi[seg];
            __nv_bfloat16* lp = (__nv_bfloat16*)a.lo[seg];
            *(__nv_bfloat162*)&hp[li * 4]     = hp0;
            *(__nv_bfloat162*)&hp[li * 4 + 2] = hp1;
            *(__nv_bfloat162*)&lp[li * 4]     = lp0;
            *(__nv_bfloat162*)&lp[li * 4 + 2] = lp1;
        }
    }
}

// ============================================================================
// K1: projection GEMM (bf16 3-pass), fp16 single output
// ============================================================================
#define PMAT  (128 * 80)
#define PSTG  (4 * PMAT)
#define P_TOT (2 * PSTG)      // 81920

__global__ __launch_bounds__(256) void proj_mma_kernel()
{
    extern __shared__ __align__(16) unsigned char dsm[];
    const uint32_t sb = smem_to_u32(dsm);

    const int tid = threadIdx.x, lane = tid & 31, wid = tid >> 5;
    const int t0 = blockIdx.x * 128;
    const int n0 = blockIdx.y * 128;
    const int sel = blockIdx.z;

    const __nv_bfloat16* Ah = g_xhi;
    const __nv_bfloat16* Al = g_xlo;
    const __nv_bfloat16* Bh = g_whi + sel * DMOD * DMOD;
    const __nv_bfloat16* Bl = g_wlo + sel * DMOD * DMOD;
    __half* outp = (sel == 0) ? g_q16 : ((sel == 1) ? g_k16 : g_v16);

    const int wm = (wid & 3) * 32;
    const int wn = (wid >> 2) * 64;
    const int lr  = (tid >> 2);
    const int seg = tid & 3;

    auto stage_load = [&](int ch, int st) {
        const int k0 = ch * 32;
        uint32_t s0 = sb + st * PSTG;
#pragma unroll
        for (int l = 0; l < 8; l++) {
            int mat = l >> 1;
            int r = (l & 1) * 64 + lr;
            const __nv_bfloat16* gp;
            int row;
            if (mat == 0)      { gp = Ah; row = t0 + r; }
            else if (mat == 1) { gp = Al; row = t0 + r; }
            else if (mat == 2) { gp = Bh; row = n0 + r; }
            else               { gp = Bl; row = n0 + r; }
            cp16(s0 + mat * PMAT + r * 80 + seg * 16,
                 &gp[row * DMOD + k0 + seg * 8]);
        }
    };

    float acc[2][8][4];
#pragma unroll
    for (int a = 0; a < 2; a++)
#pragma unroll
        for (int b = 0; b < 8; b++)
#pragma unroll
            for (int c = 0; c < 4; c++) acc[a][b][c] = 0.f;

    stage_load(0, 0);
    CP_COMMIT();

    for (int ch = 0; ch < 16; ch++) {
        const int st = ch & 1;
        if (ch + 1 < 16) { stage_load(ch + 1, st ^ 1); CP_COMMIT(); CP_WAIT(1); }
        else             { CP_WAIT(0); }
        __syncthreads();

        const uint32_t s0 = sb + st * PSTG;
#pragma unroll
        for (int s = 0; s < 2; s++) {
            uint32_t ah[2][4], al[2][4];
#pragma unroll
            for (int mi = 0; mi < 2; mi++) {
                int row = wm + mi * 16 + (lane & 15);
                uint32_t ad = s0 + row * 80 + s * 32 + ((lane >> 4) & 1) * 16;
                ldsm_x4(ad, ah[mi]);
                ldsm_x4(ad + PMAT, al[mi]);
            }
#pragma unroll
            for (int p = 0; p < 4; p++) {
                uint32_t bh[4], bl[4];
                int row = wn + p * 16 + (lane & 7) + ((lane >> 4) & 1) * 8;
                uint32_t bd = s0 + 2 * PMAT + row * 80 + s * 32 + ((lane >> 3) & 1) * 16;
                ldsm_x4(bd, bh);
                ldsm_x4(bd + PMAT, bl);
#pragma unroll
                for (int mi = 0; mi < 2; mi++)
#pragma unroll
                    for (int su = 0; su < 2; su++) {
                        mma_bf16(acc[mi][p * 2 + su], ah[mi], &bh[su * 2]);
                        mma_bf16(acc[mi][p * 2 + su], ah[mi], &bl[su * 2]);
                        mma_bf16(acc[mi][p * 2 + su], al[mi], &bh[su * 2]);
                    }
            }
        }
        __syncthreads();
    }

#pragma unroll
    for (int mi = 0; mi < 2; mi++)
#pragma unroll
        for (int ni = 0; ni < 8; ni++) {
            int e = n0 + wn + ni * 8 + (lane & 3) * 2;
            int h = e >> 6, d = e & 63;
#pragma unroll
            for (int rr = 0; rr < 2; rr++) {
                int t = t0 + wm + mi * 16 + (lane >> 2) + rr * 8;
                int m = t >> 8, i = t & 255;
                int idx = ((h * NM + m) * LQ + i) * DHH + d;
                *(uint32_t*)&outp[idx] =
                    pack_f16(acc[mi][ni][rr * 2 + 0], acc[mi][ni][rr * 2 + 1]);
            }
        }
}

// ============================================================================
// K2: e2[i][hm][j] fp16 single-pass. CTA 128(hm) x 128(j), K=64 one-shot.
// ============================================================================
#define E4_ASZ (128 * 144)    // 18432
#define E4_TOT (2 * E4_ASZ)   // 36864

__global__ __launch_bounds__(256) void e2_mma_kernel()
{
    extern __shared__ __align__(16) unsigned char dsm[];
    const uint32_t sb = smem_to_u32(dsm);

    const int tid = threadIdx.x, lane = tid & 31, wid = tid >> 5;
    const int hm0 = blockIdx.x * 128;
    const int j0  = blockIdx.y * 128;
    const int i   = blockIdx.z;
    const int wm = (wid & 3) * 32;
    const int wn = (wid >> 2) * 64;

#pragma unroll
    for (int l = 0; l < 4; l++) {
        int id = tid + l * 256;
        int r = id >> 3, c = id & 7;
        cp16(sb + r * 144 + c * 16, &g_q16[((hm0 + r) * LQ + i) * DHH + c * 8]);
        cp16(sb + E4_ASZ + r * 144 + c * 16,
             &g_ak16[(i * LQ + j0 + r) * DHH + c * 8]);
    }
    CP_COMMIT();
    CP_WAIT(0);
    __syncthreads();

    float acc[2][8][4];
#pragma unroll
    for (int a = 0; a < 2; a++)
#pragma unroll
        for (int b = 0; b < 8; b++)
#pragma unroll
            for (int c = 0; c < 4; c++) acc[a][b][c] = 0.f;

#pragma unroll
    for (int s = 0; s < 4; s++) {
        uint32_t af[2][4];
#pragma unroll
        for (int mi = 0; mi < 2; mi++) {
            uint32_t ad = sb + (wm + mi * 16 + (lane & 15)) * 144 +
                          s * 32 + ((lane >> 4) & 1) * 16;
            ldsm_x4(ad, af[mi]);
        }
#pragma unroll
        for (int p = 0; p < 4; p++) {
            uint32_t bf[4];
            uint32_t bd = sb + E4_ASZ +
                (wn + p * 16 + (lane & 7) + ((lane >> 4) & 1) * 8) * 144 +
                s * 32 + ((lane >> 3) & 1) * 16;
            ldsm_x4(bd, bf);
#pragma unroll
            for (int mi = 0; mi < 2; mi++)
#pragma unroll
                for (int su = 0; su < 2; su++)
                    mma_f16(acc[mi][p * 2 + su], af[mi], &bf[su * 2]);
        }
    }

#pragma unroll
    for (int mi = 0; mi < 2; mi++)
#pragma unroll
        for (int ni = 0; ni < 8; ni++) {
            int j = j0 + wn + ni * 8 + (lane & 3) * 2;
#pragma unroll
            for (int rr = 0; rr < 2; rr++) {
                int hm = hm0 + wm + mi * 16 + (lane >> 2) + rr * 8;
                *(float2*)&g_e2[(i * NSL + hm) * LQ + j] =
                    make_float2(acc[mi][ni][rr * 2 + 0], acc[mi][ni][rr * 2 + 1]);
            }
        }
}

// ============================================================================
// K3: fused attention, fp16 single-pass e1 + z1.
// smem: KV stage x2 (K 9216 + V 9216) | Q (128 rows fp16) = 55296
// ============================================================================
#define A4_KSZ  (64 * 144)           // 9216
#define A4_STG  (2 * A4_KSZ)         // 18432
#define A4_Q    (2 * A4_STG)         // 36864
#define A4_QSZ  (128 * 144)          // 18432
#define A4_TOT  (A4_Q + A4_QSZ)      // 55296

__global__ __launch_bounds__(256) void attn_mma_kernel()
{
    extern __shared__ __align__(16) unsigned char dsm[];
    const uint32_t sb = smem_to_u32(dsm);
    const int tid = threadIdx.x, lane = tid & 31, wid = tid >> 5;
    const int i0 = blockIdx.x * 128;
    const int hm = blockIdx.y;
    const int wm = wid * 16;
    const int gr = lane >> 2, qd = lane & 3;

    auto load_kv = [&](int jc, int st) {
        uint32_t s0 = sb + st * A4_STG;
#pragma unroll
        for (int l = 0; l < 2; l++) {
            int id = tid + l * 256;
            int r = id >> 3, c = id & 7;
            int gk = (hm * LQ + jc * 64 + r) * DHH + c * 8;
            cp16(s0 + r * 144 + c * 16, &g_k16[gk]);
            cp16(s0 + A4_KSZ + r * 144 + c * 16, &g_v16[gk]);
        }
    };

    // Q resident
#pragma unroll
    for (int l = 0; l < 4; l++) {
        int id = tid + l * 256;
        int r = id >> 3, c = id & 7;
        cp16(sb + A4_Q + r * 144 + c * 16,
             &g_q16[(hm * LQ + i0 + r) * DHH + c * 8]);
    }
    CP_COMMIT();
    load_kv(0, 0);
    CP_COMMIT();

    float accz[8][4];
#pragma unroll
    for (int b = 0; b < 8; b++)
#pragma unroll
        for (int c = 0; c < 4; c++) accz[b][c] = 0.f;
    float rsum[2] = {0.f, 0.f};

    for (int jc = 0; jc < 4; jc++) {
        const int st = jc & 1;
        __syncthreads();
        if (jc < 3) { load_kv(jc + 1, st ^ 1); CP_COMMIT(); CP_WAIT(1); }
        else        { CP_WAIT(0); }
        __syncthreads();

        const uint32_t s0 = sb + st * A4_STG;

        // ---- scores: e1 = q k^T (1 pass fp16) ----
        float acc[8][4];
#pragma unroll
        for (int b = 0; b < 8; b++)
#pragma unroll
            for (int c = 0; c < 4; c++) acc[b][c] = 0.f;

#pragma unroll
        for (int s = 0; s < 4; s++) {
            uint32_t af[4];
            uint32_t ad = sb + A4_Q + (wm + (lane & 15)) * 144 +
                          s * 32 + ((lane >> 4) & 1) * 16;
            ldsm_x4(ad, af);
#pragma unroll
            for (int p = 0; p < 4; p++) {
                uint32_t bf[4];
                uint32_t bd = s0 + (p * 16 + (lane & 7) + ((lane >> 4) & 1) * 8) * 144 +
                              s * 32 + ((lane >> 3) & 1) * 16;
                ldsm_x4(bd, bf);
#pragma unroll
                for (int su = 0; su < 2; su++)
                    mma_f16(acc[p * 2 + su], af, &bf[su * 2]);
            }
        }

        // ---- + e2, scale, exp, rowsum, pack p fp16 ----
        uint32_t pf[8][2];
        {
            int ir0 = i0 + wm + gr;
            float2 e2b0[8], e2b1[8];
#pragma unroll
            for (int ni = 0; ni < 8; ni++) {
                int col = jc * 64 + ni * 8 + qd * 2;
                e2b0[ni] = *(const float2*)&g_e2[(ir0 * NSL + hm) * LQ + col];
                e2b1[ni] = *(const float2*)&g_e2[((ir0 + 8) * NSL + hm) * LQ + col];
            }
#pragma unroll
            for (int ni = 0; ni < 8; ni++) {
                int col = jc * 64 + ni * 8 + qd * 2;
                float e0 = __expf((acc[ni][0] + e2b0[ni].x) * 0.125f);
                float e1 = __expf((acc[ni][1] + e2b0[ni].y) * 0.125f);
                float e2v = __expf((acc[ni][2] + e2b1[ni].x) * 0.125f);
                float e3 = __expf((acc[ni][3] + e2b1[ni].y) * 0.125f);
                rsum[0] += e0 + e1;
                rsum[1] += e2v + e3;
                uint32_t p01 = pack_f16(e0, e1);
                uint32_t p23 = pack_f16(e2v, e3);
                pf[ni][0] = p01; pf[ni][1] = p23;
                *(uint32_t*)&g_a16[(ir0 * NSL + hm) * LQ + col] = p01;
                *(uint32_t*)&g_a16[((ir0 + 8) * NSL + hm) * LQ + col] = p23;
            }
        }

        // ---- z1 += p V (1 pass fp16) ----
#pragma unroll
        for (int s = 0; s < 4; s++) {
            uint32_t Af[4] = {pf[2 * s][0], pf[2 * s][1],
                              pf[2 * s + 1][0], pf[2 * s + 1][1]};
#pragma unroll
            for (int p = 0; p < 4; p++) {
                uint32_t bf[4];
                uint32_t bd = s0 + A4_KSZ + (s * 16 + (lane & 15)) * 144 +
                              p * 32 + ((lane >> 4) & 1) * 16;
                ldsm_x4_t(bd, bf);
#pragma unroll
                for (int su = 0; su < 2; su++)
                    mma_f16(accz[p * 2 + su], Af, &bf[su * 2]);
            }
        }
    }

    // ---- finalize ----
    float inv[2];
#pragma unroll
    for (int rr = 0; rr < 2; rr++) {
        float r = rsum[rr];
        r += __shfl_xor_sync(0xffffffffu, r, 1);
        r += __shfl_xor_sync(0xffffffffu, r, 2);
        inv[rr] = 1.f / r;
    }
    if (qd == 0) {
#pragma unroll
        for (int rr = 0; rr < 2; rr++)
            g_invl[hm * LQ + i0 + wm + gr + rr * 8] = inv[rr];
    }
#pragma unroll
    for (int ni = 0; ni < 8; ni++)
#pragma unroll
        for (int rr = 0; rr < 2; rr++) {
            int ir = i0 + wm + gr + rr * 8;
            int d = ni * 8 + qd * 2;
            *(float2*)&g_z1[(hm * LQ + ir) * DHH + d] =
                make_float2(accz[ni][rr * 2 + 0] * inv[rr],
                            accz[ni][rr * 2 + 1] * inv[rr]);
        }
}

// ============================================================================
// K4: z2 GEMM fp16 single-pass: A = p, B = aV. 2-stage double buffer.
// ============================================================================
#define Z5_ASZ  (128 * 144)          // 18432
#define Z5_BSZ  (64 * 144)           // 9216
#define Z5_STG  (Z5_ASZ + Z5_BSZ)    // 27648
#define Z5_LINV (2 * Z5_STG)         // 55296
#define Z5_TOT  (Z5_LINV + 512)      // 55808

__global__ __launch_bounds__(256) void z2_mma_kernel()
{
    extern __shared__ __align__(16) unsigned char dsm[];
    const uint32_t sb = smem_to_u32(dsm);
    const int tid = threadIdx.x, lane = tid & 31, wid = tid >> 5;
    const int hm0 = blockIdx.x * 128;
    const int i = blockIdx.y;
    const int wm = wid * 16;
    float* linv = (float*)(dsm + Z5_LINV);

    if (tid < 128) linv[tid] = g_invl[(hm0 + tid) * LQ + i];

    auto load_chunk = [&](int jc, int st) {
        uint32_t s0 = sb + st * Z5_STG;
#pragma unroll
        for (int l = 0; l < 4; l++) {
            int id = tid + l * 256;
            int r = id >> 3, c = id & 7;
            cp16(s0 + r * 144 + c * 16,
                 &g_a16[(i * NSL + hm0 + r) * LQ + jc * 64 + c * 8]);
        }
#pragma unroll
        for (int l = 0; l < 2; l++) {
            int id = tid + l * 256;
            int r = id >> 3, c = id & 7;
            cp16(s0 + Z5_ASZ + r * 144 + c * 16,
                 &g_av16[(i * LQ + jc * 64 + r) * DHH + c * 8]);
        }
    };

    load_chunk(0, 0);
    CP_COMMIT();

    float acc[8][4];
#pragma unroll
    for (int b = 0; b < 8; b++)
#pragma unroll
        for (int c = 0; c < 4; c++) acc[b][c] = 0.f;

    for (int jc = 0; jc < 4; jc++) {
        const int st = jc & 1;
        __syncthreads();
        if (jc < 3) { load_chunk(jc + 1, st ^ 1); CP_COMMIT(); CP_WAIT(1); }
        else        { CP_WAIT(0); }
        __syncthreads();

        const uint32_t s0 = sb + st * Z5_STG;
#pragma unroll
        for (int s = 0; s < 4; s++) {
            uint32_t af[4];
            uint32_t ad = s0 + (wm + (lane & 15)) * 144 +
                          s * 32 + ((lane >> 4) & 1) * 16;
            ldsm_x4(ad, af);
#pragma unroll
            for (int p = 0; p < 4; p++) {
                uint32_t bf[4];
                uint32_t bd = s0 + Z5_ASZ + (s * 16 + (lane & 15)) * 144 +
                              p * 32 + ((lane >> 4) & 1) * 16;
                ldsm_x4_t(bd, bf);
#pragma unroll
                for (int su = 0; su < 2; su++)
                    mma_f16(acc[p * 2 + su], af, &bf[su * 2]);
            }
        }
    }

    // reduce over m (2 h-groups of 64) with invl scaling
    __syncthreads();
    float* Sf = (float*)dsm;   // [128][65]
#pragma unroll
    for (int ni = 0; ni < 8; ni++)
#pragma unroll
        for (int rr = 0; rr < 2; rr++) {
            int r = wm + (lane >> 2) + rr * 8;
            int c = ni * 8 + (lane & 3) * 2;
            Sf[r * 65 + c]     = acc[ni][rr * 2 + 0];
            Sf[r * 65 + c + 1] = acc[ni][rr * 2 + 1];
        }
    __syncthreads();
    if (tid < 128) {
        int g = tid >> 6, d = tid & 63;
        float s = 0.f;
#pragma unroll 8
        for (int m = 0; m < 64; m++)
            s += Sf[(g * 64 + m) * 65 + d] * linv[g * 64 + m];
        int h = blockIdx.x * 2 + g;
        g_z2[(i * NH + h) * DHH + d] = s;
    }
}

// =============================================================================
// K5: out
// =============================================================================
__global__ __launch_bounds__(256) void final_kernel(float* __restrict__ out)
{
    int g = blockIdx.x * 256 + threadIdx.x;
    int i = g >> 9;
    int rest = g & 511;
    int h = rest >> 6;
    int d = rest & 63;

    const float* zp = &g_z1[((h * NM) * LQ + i) * DHH + d];
    float s = g_z2[(i * NH + h) * DHH + d];
#pragma unroll 8
    for (int m = 0; m < 64; m++) s += zp[m * (LQ * DHH)];
    out[g] = s;
}

// =============================================================================
extern "C" void kernel_launch(void* const* d_in, const int* in_sizes, int n_in,
                              void* d_out, int out_size)
{
    const float* x  = (const float*)d_in[0];
    const float* Wq = (const float*)d_in[1];
    const float* Wk = (const float*)d_in[2];
    const float* Wv = (const float*)d_in[3];
    const float* aK = (const float*)d_in[4];
    const float* aV = (const float*)d_in[5];
    float* out = (float*)d_out;

    cudaFuncSetAttribute(proj_mma_kernel,
                         cudaFuncAttributeMaxDynamicSharedMemorySize, P_TOT);
    cudaFuncSetAttribute(e2_mma_kernel,
                         cudaFuncAttributeMaxDynamicSharedMemorySize, E4_TOT);
    cudaFuncSetAttribute(attn_mma_kernel,
                         cudaFuncAttributeMaxDynamicSharedMemorySize, A4_TOT);
    cudaFuncSetAttribute(z2_mma_kernel,
                         cudaFuncAttributeMaxDynamicSharedMemorySize, Z5_TOT);

    void *xhi_p, *xlo_p, *whi_p, *wlo_p, *ak_p, *av_p;
    cudaGetSymbolAddress(&xhi_p, g_xhi);
    cudaGetSymbolAddress(&xlo_p, g_xlo);
    cudaGetSymbolAddress(&whi_p, g_whi);
    cudaGetSymbolAddress(&wlo_p, g_wlo);
    cudaGetSymbolAddress(&ak_p,  g_ak16);
    cudaGetSymbolAddress(&av_p,  g_av16);

    SplitArgs sa;
    sa.src[0] = x;  sa.hi[0] = xhi_p;  sa.lo[0] = xlo_p;
    sa.src[1] = Wq; sa.hi[1] = whi_p;  sa.lo[1] = wlo_p;
    sa.src[2] = Wk; sa.hi[2] = (__nv_bfloat16*)whi_p + DMOD * DMOD;
                    sa.lo[2] = (__nv_bfloat16*)wlo_p + DMOD * DMOD;
    sa.src[3] = Wv; sa.hi[3] = (__nv_bfloat16*)whi_p + 2 * DMOD * DMOD;
                    sa.lo[3] = (__nv_bfloat16*)wlo_p + 2 * DMOD * DMOD;
    sa.src[4] = aK; sa.hi[4] = ak_p; sa.lo[4] = nullptr;
    sa.src[5] = aV; sa.hi[5] = av_p; sa.lo[5] = nullptr;
    int nv[6] = {NTOK * DMOD / 4, DMOD * DMOD / 4, DMOD * DMOD / 4,
                 DMOD * DMOD / 4, LQ * LQ * DHH / 4, LQ * LQ * DHH / 4};
    sa.off[0] = 0;
    for (int s = 0; s < 6; s++) sa.off[s + 1] = sa.off[s] + nv[s];

    split_all_kernel<<<4096, 256>>>(sa);

    proj_mma_kernel<<<dim3(NTOK / 128, DMOD / 128, 3), 256, P_TOT>>>();
    e2_mma_kernel<<<dim3(4, 2, LQ), 256, E4_TOT>>>();
    attn_mma_kernel<<<dim3(2, NSL), 256, A4_TOT>>>();
    z2_mma_kernel<<<dim3(4, LQ), 256, Z5_TOT>>>();
    final_kernel<<<512, 256>>>(out);
}

// round 12
// speedup vs baseline: 2.0515x; 1.4874x over previous
#include <cuda_runtime.h>
#include <cuda_bf16.h>
#include <cuda_fp16.h>
#include <cstdint>
#include <math.h>

#define LQ   256
#define DHH  64
#define NH   8
#define NM   64
#define NSL  (NH*NM)   // 512
#define DMOD 512
#define NTOK (NM*LQ)   // 16384

// ---------------- scratch -------------
__device__ float g_z1[NSL * LQ * DHH];       // [hm][i][d]
__device__ float g_z2[LQ * NH * DHH];        // [i][h][d]
__device__ float g_invl[NSL * LQ];           // [hm][i]

__device__ __half g_x16[NTOK * DMOD];
__device__ __half g_w16[3 * DMOD * DMOD];
__device__ __half g_q16[NSL * LQ * DHH];     // [hm][i][d]
__device__ __half g_k16[NSL * LQ * DHH];
__device__ __half g_v16[NSL * LQ * DHH];
__device__ __half g_ak16[LQ * LQ * DHH];     // [i][j][d]
__device__ __half g_av16[LQ * LQ * DHH];
__device__ __half g_e16[LQ * NSL * LQ];      // e2 fp16 [i][hm][j]
__device__ __half g_a16[LQ * NSL * LQ];      // unnormalized p fp16 [i][hm][j]

// ========================= helpers ==================================
__device__ __forceinline__ uint32_t smem_to_u32(const void* p) {
    uint32_t a;
    asm("{ .reg .u64 t; cvta.to.shared.u64 t, %1; cvt.u32.u64 %0, t; }"
        : "=r"(a) : "l"(p));
    return a;
}
__device__ __forceinline__ void ldsm_x4(uint32_t addr, uint32_t* r) {
    asm volatile("ldmatrix.sync.aligned.m8n8.x4.shared.b16 {%0,%1,%2,%3}, [%4];"
        : "=r"(r[0]), "=r"(r[1]), "=r"(r[2]), "=r"(r[3]) : "r"(addr));
}
__device__ __forceinline__ void ldsm_x4_t(uint32_t addr, uint32_t* r) {
    asm volatile("ldmatrix.sync.aligned.m8n8.x4.trans.shared.b16 {%0,%1,%2,%3}, [%4];"
        : "=r"(r[0]), "=r"(r[1]), "=r"(r[2]), "=r"(r[3]) : "r"(addr));
}
__device__ __forceinline__ void mma_f16(float* c, const uint32_t* a,
                                        const uint32_t* b) {
    asm volatile(
        "mma.sync.aligned.m16n8k16.row.col.f32.f16.f16.f32 "
        "{%0,%1,%2,%3}, {%4,%5,%6,%7}, {%8,%9}, {%0,%1,%2,%3};"
        : "+f"(c[0]), "+f"(c[1]), "+f"(c[2]), "+f"(c[3])
        : "r"(a[0]), "r"(a[1]), "r"(a[2]), "r"(a[3]), "r"(b[0]), "r"(b[1]));
}
__device__ __forceinline__ uint32_t pack_f16(float a, float b) {
    __half2 h(__float2half(a), __float2half(b));
    return *(uint32_t*)&h;
}
__device__ __forceinline__ void cp16(uint32_t s, const void* g) {
    asm volatile("cp.async.cg.shared.global [%0], [%1], 16;"
                 :: "r"(s), "l"(g) : "memory");
}
#define CP_COMMIT() asm volatile("cp.async.commit_group;" ::: "memory")
#define CP_WAIT(n)  asm volatile("cp.async.wait_group %0;" :: "n"(n) : "memory")

// ============================================================================
// merged convert: all 6 tensors fp32 -> single fp16
// ============================================================================
struct SplitArgs {
    const float* src[6];
    __half* dst[6];
    int off[7];
};

__global__ __launch_bounds__(256) void split_all_kernel(SplitArgs a)
{
    int total = a.off[6];
    for (int idx = blockIdx.x * 256 + threadIdx.x; idx < total;
         idx += gridDim.x * 256) {
        int seg = 0;
#pragma unroll
        for (int s = 1; s < 6; s++) if (idx >= a.off[s]) seg = s;
        int li = idx - a.off[seg];
        float4 v = *(const float4*)&a.src[seg][li * 4];
        __half2 a01(__float2half(v.x), __float2half(v.y));
        __half2 a23(__float2half(v.z), __float2half(v.w));
        __half* dp = a.dst[seg];
        *(__half2*)&dp[li * 4]     = a01;
        *(__half2*)&dp[li * 4 + 2] = a23;
    }
}

// ============================================================================
// K1: projection GEMM, single-pass fp16. CTA 128x128, K=512 in 16 chunks,
// cp.async 2-stage.
// ============================================================================
#define PMAT  (128 * 80)      // 10240
#define PSTG  (2 * PMAT)      // 20480
#define P_TOT (2 * PSTG)      // 40960

__global__ __launch_bounds__(256) void proj_mma_kernel()
{
    extern __shared__ __align__(16) unsigned char dsm[];
    const uint32_t sb = smem_to_u32(dsm);

    const int tid = threadIdx.x, lane = tid & 31, wid = tid >> 5;
    const int t0 = blockIdx.x * 128;
    const int n0 = blockIdx.y * 128;
    const int sel = blockIdx.z;

    const __half* A = g_x16;
    const __half* B = g_w16 + sel * DMOD * DMOD;
    __half* outp = (sel == 0) ? g_q16 : ((sel == 1) ? g_k16 : g_v16);

    const int wm = (wid & 3) * 32;
    const int wn = (wid >> 2) * 64;
    const int lr  = (tid >> 2);
    const int seg = tid & 3;

    auto stage_load = [&](int ch, int st) {
        const int k0 = ch * 32;
        uint32_t s0 = sb + st * PSTG;
#pragma unroll
        for (int l = 0; l < 4; l++) {
            int mat = l >> 1;
            int r = (l & 1) * 64 + lr;
            const __half* gp = mat ? B : A;
            int row = (mat ? n0 : t0) + r;
            cp16(s0 + mat * PMAT + r * 80 + seg * 16,
                 &gp[row * DMOD + k0 + seg * 8]);
        }
    };

    float acc[2][8][4];
#pragma unroll
    for (int a = 0; a < 2; a++)
#pragma unroll
        for (int b = 0; b < 8; b++)
#pragma unroll
            for (int c = 0; c < 4; c++) acc[a][b][c] = 0.f;

    stage_load(0, 0);
    CP_COMMIT();

    for (int ch = 0; ch < 16; ch++) {
        const int st = ch & 1;
        if (ch + 1 < 16) { stage_load(ch + 1, st ^ 1); CP_COMMIT(); CP_WAIT(1); }
        else             { CP_WAIT(0); }
        __syncthreads();

        const uint32_t s0 = sb + st * PSTG;
#pragma unroll
        for (int s = 0; s < 2; s++) {
            uint32_t af[2][4];
#pragma unroll
            for (int mi = 0; mi < 2; mi++) {
                int row = wm + mi * 16 + (lane & 15);
                uint32_t ad = s0 + row * 80 + s * 32 + ((lane >> 4) & 1) * 16;
                ldsm_x4(ad, af[mi]);
            }
#pragma unroll
            for (int p = 0; p < 4; p++) {
                uint32_t bf[4];
                int row = wn + p * 16 + (lane & 7) + ((lane >> 4) & 1) * 8;
                uint32_t bd = s0 + PMAT + row * 80 + s * 32 + ((lane >> 3) & 1) * 16;
                ldsm_x4(bd, bf);
#pragma unroll
                for (int mi = 0; mi < 2; mi++)
#pragma unroll
                    for (int su = 0; su < 2; su++)
                        mma_f16(acc[mi][p * 2 + su], af[mi], &bf[su * 2]);
            }
        }
        __syncthreads();
    }

#pragma unroll
    for (int mi = 0; mi < 2; mi++)
#pragma unroll
        for (int ni = 0; ni < 8; ni++) {
            int e = n0 + wn + ni * 8 + (lane & 3) * 2;
            int h = e >> 6, d = e & 63;
#pragma unroll
            for (int rr = 0; rr < 2; rr++) {
                int t = t0 + wm + mi * 16 + (lane >> 2) + rr * 8;
                int m = t >> 8, i = t & 255;
                int idx = ((h * NM + m) * LQ + i) * DHH + d;
                *(uint32_t*)&outp[idx] =
                    pack_f16(acc[mi][ni][rr * 2 + 0], acc[mi][ni][rr * 2 + 1]);
            }
        }
}

// ============================================================================
// K2: e2[i][hm][j] fp16 single-pass, fp16 output. CTA 128x128, K=64 one-shot.
// ============================================================================
#define E4_ASZ (128 * 144)    // 18432
#define E4_TOT (2 * E4_ASZ)   // 36864

__global__ __launch_bounds__(256) void e2_mma_kernel()
{
    extern __shared__ __align__(16) unsigned char dsm[];
    const uint32_t sb = smem_to_u32(dsm);

    const int tid = threadIdx.x, lane = tid & 31, wid = tid >> 5;
    const int hm0 = blockIdx.x * 128;
    const int j0  = blockIdx.y * 128;
    const int i   = blockIdx.z;
    const int wm = (wid & 3) * 32;
    const int wn = (wid >> 2) * 64;

#pragma unroll
    for (int l = 0; l < 4; l++) {
        int id = tid + l * 256;
        int r = id >> 3, c = id & 7;
        cp16(sb + r * 144 + c * 16, &g_q16[((hm0 + r) * LQ + i) * DHH + c * 8]);
        cp16(sb + E4_ASZ + r * 144 + c * 16,
             &g_ak16[(i * LQ + j0 + r) * DHH + c * 8]);
    }
    CP_COMMIT();
    CP_WAIT(0);
    __syncthreads();

    float acc[2][8][4];
#pragma unroll
    for (int a = 0; a < 2; a++)
#pragma unroll
        for (int b = 0; b < 8; b++)
#pragma unroll
            for (int c = 0; c < 4; c++) acc[a][b][c] = 0.f;

#pragma unroll
    for (int s = 0; s < 4; s++) {
        uint32_t af[2][4];
#pragma unroll
        for (int mi = 0; mi < 2; mi++) {
            uint32_t ad = sb + (wm + mi * 16 + (lane & 15)) * 144 +
                          s * 32 + ((lane >> 4) & 1) * 16;
            ldsm_x4(ad, af[mi]);
        }
#pragma unroll
        for (int p = 0; p < 4; p++) {
            uint32_t bf[4];
            uint32_t bd = sb + E4_ASZ +
                (wn + p * 16 + (lane & 7) + ((lane >> 4) & 1) * 8) * 144 +
                s * 32 + ((lane >> 3) & 1) * 16;
            ldsm_x4(bd, bf);
#pragma unroll
            for (int mi = 0; mi < 2; mi++)
#pragma unroll
                for (int su = 0; su < 2; su++)
                    mma_f16(acc[mi][p * 2 + su], af[mi], &bf[su * 2]);
        }
    }

#pragma unroll
    for (int mi = 0; mi < 2; mi++)
#pragma unroll
        for (int ni = 0; ni < 8; ni++) {
            int j = j0 + wn + ni * 8 + (lane & 3) * 2;
#pragma unroll
            for (int rr = 0; rr < 2; rr++) {
                int hm = hm0 + wm + mi * 16 + (lane >> 2) + rr * 8;
                *(uint32_t*)&g_e16[(i * NSL + hm) * LQ + j] =
                    pack_f16(acc[mi][ni][rr * 2 + 0], acc[mi][ni][rr * 2 + 1]);
            }
        }
}

// ============================================================================
// K3: fused attention, fp16 single-pass; e2 read as fp16
// ============================================================================
#define A4_KSZ  (64 * 144)           // 9216
#define A4_STG  (2 * A4_KSZ)         // 18432
#define A4_Q    (2 * A4_STG)         // 36864
#define A4_QSZ  (128 * 144)          // 18432
#define A4_TOT  (A4_Q + A4_QSZ)      // 55296

__global__ __launch_bounds__(256) void attn_mma_kernel()
{
    extern __shared__ __align__(16) unsigned char dsm[];
    const uint32_t sb = smem_to_u32(dsm);
    const int tid = threadIdx.x, lane = tid & 31, wid = tid >> 5;
    const int i0 = blockIdx.x * 128;
    const int hm = blockIdx.y;
    const int wm = wid * 16;
    const int gr = lane >> 2, qd = lane & 3;

    auto load_kv = [&](int jc, int st) {
        uint32_t s0 = sb + st * A4_STG;
#pragma unroll
        for (int l = 0; l < 2; l++) {
            int id = tid + l * 256;
            int r = id >> 3, c = id & 7;
            int gk = (hm * LQ + jc * 64 + r) * DHH + c * 8;
            cp16(s0 + r * 144 + c * 16, &g_k16[gk]);
            cp16(s0 + A4_KSZ + r * 144 + c * 16, &g_v16[gk]);
        }
    };

    // Q resident
#pragma unroll
    for (int l = 0; l < 4; l++) {
        int id = tid + l * 256;
        int r = id >> 3, c = id & 7;
        cp16(sb + A4_Q + r * 144 + c * 16,
             &g_q16[(hm * LQ + i0 + r) * DHH + c * 8]);
    }
    CP_COMMIT();
    load_kv(0, 0);
    CP_COMMIT();

    float accz[8][4];
#pragma unroll
    for (int b = 0; b < 8; b++)
#pragma unroll
        for (int c = 0; c < 4; c++) accz[b][c] = 0.f;
    float rsum[2] = {0.f, 0.f};

    for (int jc = 0; jc < 4; jc++) {
        const int st = jc & 1;
        __syncthreads();
        if (jc < 3) { load_kv(jc + 1, st ^ 1); CP_COMMIT(); CP_WAIT(1); }
        else        { CP_WAIT(0); }
        __syncthreads();

        const uint32_t s0 = sb + st * A4_STG;

        // ---- scores: e1 = q k^T ----
        float acc[8][4];
#pragma unroll
        for (int b = 0; b < 8; b++)
#pragma unroll
            for (int c = 0; c < 4; c++) acc[b][c] = 0.f;

#pragma unroll
        for (int s = 0; s < 4; s++) {
            uint32_t af[4];
            uint32_t ad = sb + A4_Q + (wm + (lane & 15)) * 144 +
                          s * 32 + ((lane >> 4) & 1) * 16;
            ldsm_x4(ad, af);
#pragma unroll
            for (int p = 0; p < 4; p++) {
                uint32_t bf[4];
                uint32_t bd = s0 + (p * 16 + (lane & 7) + ((lane >> 4) & 1) * 8) * 144 +
                              s * 32 + ((lane >> 3) & 1) * 16;
                ldsm_x4(bd, bf);
#pragma unroll
                for (int su = 0; su < 2; su++)
                    mma_f16(acc[p * 2 + su], af, &bf[su * 2]);
            }
        }

        // ---- + e2(fp16), scale, exp, rowsum, pack p fp16 ----
        uint32_t pf[8][2];
        {
            int ir0 = i0 + wm + gr;
            __half2 e2b0[8], e2b1[8];
#pragma unroll
            for (int ni = 0; ni < 8; ni++) {
                int col = jc * 64 + ni * 8 + qd * 2;
                e2b0[ni] = *(const __half2*)&g_e16[(ir0 * NSL + hm) * LQ + col];
                e2b1[ni] = *(const __half2*)&g_e16[((ir0 + 8) * NSL + hm) * LQ + col];
            }
#pragma unroll
            for (int ni = 0; ni < 8; ni++) {
                int col = jc * 64 + ni * 8 + qd * 2;
                float e0 = __expf((acc[ni][0] + __half2float(e2b0[ni].x)) * 0.125f);
                float e1 = __expf((acc[ni][1] + __half2float(e2b0[ni].y)) * 0.125f);
                float e2v = __expf((acc[ni][2] + __half2float(e2b1[ni].x)) * 0.125f);
                float e3 = __expf((acc[ni][3] + __half2float(e2b1[ni].y)) * 0.125f);
                rsum[0] += e0 + e1;
                rsum[1] += e2v + e3;
                uint32_t p01 = pack_f16(e0, e1);
                uint32_t p23 = pack_f16(e2v, e3);
                pf[ni][0] = p01; pf[ni][1] = p23;
                *(uint32_t*)&g_a16[(ir0 * NSL + hm) * LQ + col] = p01;
                *(uint32_t*)&g_a16[((ir0 + 8) * NSL + hm) * LQ + col] = p23;
            }
        }

        // ---- z1 += p V ----
#pragma unroll
        for (int s = 0; s < 4; s++) {
            uint32_t Af[4] = {pf[2 * s][0], pf[2 * s][1],
                              pf[2 * s + 1][0], pf[2 * s + 1][1]};
#pragma unroll
            for (int p = 0; p < 4; p++) {
                uint32_t bf[4];
                uint32_t bd = s0 + A4_KSZ + (s * 16 + (lane & 15)) * 144 +
                              p * 32 + ((lane >> 4) & 1) * 16;
                ldsm_x4_t(bd, bf);
#pragma unroll
                for (int su = 0; su < 2; su++)
                    mma_f16(accz[p * 2 + su], Af, &bf[su * 2]);
            }
        }
    }

    // ---- finalize ----
    float inv[2];
#pragma unroll
    for (int rr = 0; rr < 2; rr++) {
        float r = rsum[rr];
        r += __shfl_xor_sync(0xffffffffu, r, 1);
        r += __shfl_xor_sync(0xffffffffu, r, 2);
        inv[rr] = 1.f / r;
    }
    if (qd == 0) {
#pragma unroll
        for (int rr = 0; rr < 2; rr++)
            g_invl[hm * LQ + i0 + wm + gr + rr * 8] = inv[rr];
    }
#pragma unroll
    for (int ni = 0; ni < 8; ni++)
#pragma unroll
        for (int rr = 0; rr < 2; rr++) {
            int ir = i0 + wm + gr + rr * 8;
            int d = ni * 8 + qd * 2;
            *(float2*)&g_z1[(hm * LQ + ir) * DHH + d] =
                make_float2(accz[ni][rr * 2 + 0] * inv[rr],
                            accz[ni][rr * 2 + 1] * inv[rr]);
        }
}

// ============================================================================
// K4: z2 GEMM fp16 single-pass, 2-stage double buffer, invl in reduction
// ============================================================================
#define Z5_ASZ  (128 * 144)          // 18432
#define Z5_BSZ  (64 * 144)           // 9216
#define Z5_STG  (Z5_ASZ + Z5_BSZ)    // 27648
#define Z5_LINV (2 * Z5_STG)         // 55296
#define Z5_TOT  (Z5_LINV + 512)      // 55808

__global__ __launch_bounds__(256) void z2_mma_kernel()
{
    extern __shared__ __align__(16) unsigned char dsm[];
    const uint32_t sb = smem_to_u32(dsm);
    const int tid = threadIdx.x, lane = tid & 31, wid = tid >> 5;
    const int hm0 = blockIdx.x * 128;
    const int i = blockIdx.y;
    const int wm = wid * 16;
    float* linv = (float*)(dsm + Z5_LINV);

    if (tid < 128) linv[tid] = g_invl[(hm0 + tid) * LQ + i];

    auto load_chunk = [&](int jc, int st) {
        uint32_t s0 = sb + st * Z5_STG;
#pragma unroll
        for (int l = 0; l < 4; l++) {
            int id = tid + l * 256;
            int r = id >> 3, c = id & 7;
            cp16(s0 + r * 144 + c * 16,
                 &g_a16[(i * NSL + hm0 + r) * LQ + jc * 64 + c * 8]);
        }
#pragma unroll
        for (int l = 0; l < 2; l++) {
            int id = tid + l * 256;
            int r = id >> 3, c = id & 7;
            cp16(s0 + Z5_ASZ + r * 144 + c * 16,
                 &g_av16[(i * LQ + jc * 64 + r) * DHH + c * 8]);
        }
    };

    load_chunk(0, 0);
    CP_COMMIT();

    float acc[8][4];
#pragma unroll
    for (int b = 0; b < 8; b++)
#pragma unroll
        for (int c = 0; c < 4; c++) acc[b][c] = 0.f;

    for (int jc = 0; jc < 4; jc++) {
        const int st = jc & 1;
        __syncthreads();
        if (jc < 3) { load_chunk(jc + 1, st ^ 1); CP_COMMIT(); CP_WAIT(1); }
        else        { CP_WAIT(0); }
        __syncthreads();

        const uint32_t s0 = sb + st * Z5_STG;
#pragma unroll
        for (int s = 0; s < 4; s++) {
            uint32_t af[4];
            uint32_t ad = s0 + (wm + (lane & 15)) * 144 +
                          s * 32 + ((lane >> 4) & 1) * 16;
            ldsm_x4(ad, af);
#pragma unroll
            for (int p = 0; p < 4; p++) {
                uint32_t bf[4];
                uint32_t bd = s0 + Z5_ASZ + (s * 16 + (lane & 15)) * 144 +
                              p * 32 + ((lane >> 4) & 1) * 16;
                ldsm_x4_t(bd, bf);
#pragma unroll
                for (int su = 0; su < 2; su++)
                    mma_f16(acc[p * 2 + su], af, &bf[su * 2]);
            }
        }
    }

    // reduce over m (2 h-groups of 64) with invl scaling
    __syncthreads();
    float* Sf = (float*)dsm;   // [128][65]
#pragma unroll
    for (int ni = 0; ni < 8; ni++)
#pragma unroll
        for (int rr = 0; rr < 2; rr++) {
            int r = wm + (lane >> 2) + rr * 8;
            int c = ni * 8 + (lane & 3) * 2;
            Sf[r * 65 + c]     = acc[ni][rr * 2 + 0];
            Sf[r * 65 + c + 1] = acc[ni][rr * 2 + 1];
        }
    __syncthreads();
    if (tid < 128) {
        int g = tid >> 6, d = tid & 63;
        float s = 0.f;
#pragma unroll 8
        for (int m = 0; m < 64; m++)
            s += Sf[(g * 64 + m) * 65 + d] * linv[g * 64 + m];
        int h = blockIdx.x * 2 + g;
        g_z2[(i * NH + h) * DHH + d] = s;
    }
}

// =============================================================================
// K5: out
// =============================================================================
__global__ __launch_bounds__(256) void final_kernel(float* __restrict__ out)
{
    int g = blockIdx.x * 256 + threadIdx.x;
    int i = g >> 9;
    int rest = g & 511;
    int h = rest >> 6;
    int d = rest & 63;

    const float* zp = &g_z1[((h * NM) * LQ + i) * DHH + d];
    float s = g_z2[(i * NH + h) * DHH + d];
#pragma unroll 8
    for (int m = 0; m < 64; m++) s += zp[m * (LQ * DHH)];
    out[g] = s;
}

// =============================================================================
extern "C" void kernel_launch(void* const* d_in, const int* in_sizes, int n_in,
                              void* d_out, int out_size)
{
    const float* x  = (const float*)d_in[0];
    const float* Wq = (const float*)d_in[1];
    const float* Wk = (const float*)d_in[2];
    const float* Wv = (const float*)d_in[3];
    const float* aK = (const float*)d_in[4];
    const float* aV = (const float*)d_in[5];
    float* out = (float*)d_out;

    cudaFuncSetAttribute(proj_mma_kernel,
                         cudaFuncAttributeMaxDynamicSharedMemorySize, P_TOT);
    cudaFuncSetAttribute(e2_mma_kernel,
                         cudaFuncAttributeMaxDynamicSharedMemorySize, E4_TOT);
    cudaFuncSetAttribute(attn_mma_kernel,
                         cudaFuncAttributeMaxDynamicSharedMemorySize, A4_TOT);
    cudaFuncSetAttribute(z2_mma_kernel,
                         cudaFuncAttributeMaxDynamicSharedMemorySize, Z5_TOT);

    void *x_p, *w_p, *ak_p, *av_p;
    cudaGetSymbolAddress(&x_p,  g_x16);
    cudaGetSymbolAddress(&w_p,  g_w16);
    cudaGetSymbolAddress(&ak_p, g_ak16);
    cudaGetSymbolAddress(&av_p, g_av16);

    SplitArgs sa;
    sa.src[0] = x;  sa.dst[0] = (__half*)x_p;
    sa.src[1] = Wq; sa.dst[1] = (__half*)w_p;
    sa.src[2] = Wk; sa.dst[2] = (__half*)w_p + DMOD * DMOD;
    sa.src[3] = Wv; sa.dst[3] = (__half*)w_p + 2 * DMOD * DMOD;
    sa.src[4] = aK; sa.dst[4] = (__half*)ak_p;
    sa.src[5] = aV; sa.dst[5] = (__half*)av_p;
    int nv[6] = {NTOK * DMOD / 4, DMOD * DMOD / 4, DMOD * DMOD / 4,
                 DMOD * DMOD / 4, LQ * LQ * DHH / 4, LQ * LQ * DHH / 4};
    sa.off[0] = 0;
    for (int s = 0; s < 6; s++) sa.off[s + 1] = sa.off[s] + nv[s];

    split_all_kernel<<<4096, 256>>>(sa);

    proj_mma_kernel<<<dim3(NTOK / 128, DMOD / 128, 3), 256, P_TOT>>>();
    e2_mma_kernel<<<dim3(4, 2, LQ), 256, E4_TOT>>>();
    attn_mma_kernel<<<dim3(2, NSL), 256, A4_TOT>>>();
    z2_mma_kernel<<<dim3(4, LQ), 256, Z5_TOT>>>();
    final_kernel<<<512, 256>>>(out);
}

// round 13
// speedup vs baseline: 2.0517x; 1.0001x over previous
#include <cuda_runtime.h>
#include <cuda_bf16.h>
#include <cuda_fp16.h>
#include <cstdint>
#include <math.h>

#define LQ   256
#define DHH  64
#define NH   8
#define NM   64
#define NSL  (NH*NM)   // 512
#define DMOD 512
#define NTOK (NM*LQ)   // 16384

// ---------------- scratch -------------
__device__ float g_z1[NSL * LQ * DHH];       // [hm][i][d]
__device__ float g_z2[LQ * NH * DHH];        // [i][h][d]
__device__ float g_invl[NSL * LQ];           // [hm][i]

__device__ __half g_x16[NTOK * DMOD];
__device__ __half g_w16[3 * DMOD * DMOD];
__device__ __half g_q16[NSL * LQ * DHH];     // [hm][i][d]
__device__ __half g_k16[NSL * LQ * DHH];
__device__ __half g_v16[NSL * LQ * DHH];
__device__ __half g_ak16[LQ * LQ * DHH];     // [i][j][d]
__device__ __half g_av16[LQ * LQ * DHH];
__device__ __half g_e16[LQ * NSL * LQ];      // e2 fp16 [i][hm][j]
__device__ __half g_a16[LQ * NSL * LQ];      // unnormalized p fp16 [i][hm][j]

// ========================= helpers ==================================
__device__ __forceinline__ uint32_t smem_to_u32(const void* p) {
    uint32_t a;
    asm("{ .reg .u64 t; cvta.to.shared.u64 t, %1; cvt.u32.u64 %0, t; }"
        : "=r"(a) : "l"(p));
    return a;
}
__device__ __forceinline__ void ldsm_x4(uint32_t addr, uint32_t* r) {
    asm volatile("ldmatrix.sync.aligned.m8n8.x4.shared.b16 {%0,%1,%2,%3}, [%4];"
        : "=r"(r[0]), "=r"(r[1]), "=r"(r[2]), "=r"(r[3]) : "r"(addr));
}
__device__ __forceinline__ void ldsm_x4_t(uint32_t addr, uint32_t* r) {
    asm volatile("ldmatrix.sync.aligned.m8n8.x4.trans.shared.b16 {%0,%1,%2,%3}, [%4];"
        : "=r"(r[0]), "=r"(r[1]), "=r"(r[2]), "=r"(r[3]) : "r"(addr));
}
__device__ __forceinline__ void mma_f16(float* c, const uint32_t* a,
                                        const uint32_t* b) {
    asm volatile(
        "mma.sync.aligned.m16n8k16.row.col.f32.f16.f16.f32 "
        "{%0,%1,%2,%3}, {%4,%5,%6,%7}, {%8,%9}, {%0,%1,%2,%3};"
        : "+f"(c[0]), "+f"(c[1]), "+f"(c[2]), "+f"(c[3])
        : "r"(a[0]), "r"(a[1]), "r"(a[2]), "r"(a[3]), "r"(b[0]), "r"(b[1]));
}
__device__ __forceinline__ uint32_t pack_f16(float a, float b) {
    __half2 h(__float2half(a), __float2half(b));
    return *(uint32_t*)&h;
}
__device__ __forceinline__ void cp16(uint32_t s, const void* g) {
    asm volatile("cp.async.cg.shared.global [%0], [%1], 16;"
                 :: "r"(s), "l"(g) : "memory");
}
#define CP_COMMIT() asm volatile("cp.async.commit_group;" ::: "memory")
#define CP_WAIT(n)  asm volatile("cp.async.wait_group %0;" :: "n"(n) : "memory")

// ============================================================================
// merged convert: all 6 tensors fp32 -> single fp16
// ============================================================================
struct SplitArgs {
    const float* src[6];
    __half* dst[6];
    int off[7];
};

__global__ __launch_bounds__(256) void split_all_kernel(SplitArgs a)
{
    int total = a.off[6];
    for (int idx = blockIdx.x * 256 + threadIdx.x; idx < total;
         idx += gridDim.x * 256) {
        int seg = 0;
#pragma unroll
        for (int s = 1; s < 6; s++) if (idx >= a.off[s]) seg = s;
        int li = idx - a.off[seg];
        float4 v = *(const float4*)&a.src[seg][li * 4];
        __half2 a01(__float2half(v.x), __float2half(v.y));
        __half2 a23(__float2half(v.z), __float2half(v.w));
        __half* dp = a.dst[seg];
        *(__half2*)&dp[li * 4]     = a01;
        *(__half2*)&dp[li * 4 + 2] = a23;
    }
}

// ============================================================================
// K1: projection GEMM, single-pass fp16. CTA 128x128, K=512 in 16 chunks,
// cp.async 2-stage.
// ============================================================================
#define PMAT  (128 * 80)      // 10240
#define PSTG  (2 * PMAT)      // 20480
#define P_TOT (2 * PSTG)      // 40960

__global__ __launch_bounds__(256) void proj_mma_kernel()
{
    extern __shared__ __align__(16) unsigned char dsm[];
    const uint32_t sb = smem_to_u32(dsm);

    const int tid = threadIdx.x, lane = tid & 31, wid = tid >> 5;
    const int t0 = blockIdx.x * 128;
    const int n0 = blockIdx.y * 128;
    const int sel = blockIdx.z;

    const __half* A = g_x16;
    const __half* B = g_w16 + sel * DMOD * DMOD;
    __half* outp = (sel == 0) ? g_q16 : ((sel == 1) ? g_k16 : g_v16);

    const int wm = (wid & 3) * 32;
    const int wn = (wid >> 2) * 64;
    const int lr  = (tid >> 2);
    const int seg = tid & 3;

    auto stage_load = [&](int ch, int st) {
        const int k0 = ch * 32;
        uint32_t s0 = sb + st * PSTG;
#pragma unroll
        for (int l = 0; l < 4; l++) {
            int mat = l >> 1;
            int r = (l & 1) * 64 + lr;
            const __half* gp = mat ? B : A;
            int row = (mat ? n0 : t0) + r;
            cp16(s0 + mat * PMAT + r * 80 + seg * 16,
                 &gp[row * DMOD + k0 + seg * 8]);
        }
    };

    float acc[2][8][4];
#pragma unroll
    for (int a = 0; a < 2; a++)
#pragma unroll
        for (int b = 0; b < 8; b++)
#pragma unroll
            for (int c = 0; c < 4; c++) acc[a][b][c] = 0.f;

    stage_load(0, 0);
    CP_COMMIT();

    for (int ch = 0; ch < 16; ch++) {
        const int st = ch & 1;
        if (ch + 1 < 16) { stage_load(ch + 1, st ^ 1); CP_COMMIT(); CP_WAIT(1); }
        else             { CP_WAIT(0); }
        __syncthreads();

        const uint32_t s0 = sb + st * PSTG;
#pragma unroll
        for (int s = 0; s < 2; s++) {
            uint32_t af[2][4];
#pragma unroll
            for (int mi = 0; mi < 2; mi++) {
                int row = wm + mi * 16 + (lane & 15);
                uint32_t ad = s0 + row * 80 + s * 32 + ((lane >> 4) & 1) * 16;
                ldsm_x4(ad, af[mi]);
            }
#pragma unroll
            for (int p = 0; p < 4; p++) {
                uint32_t bf[4];
                int row = wn + p * 16 + (lane & 7) + ((lane >> 4) & 1) * 8;
                uint32_t bd = s0 + PMAT + row * 80 + s * 32 + ((lane >> 3) & 1) * 16;
                ldsm_x4(bd, bf);
#pragma unroll
                for (int mi = 0; mi < 2; mi++)
#pragma unroll
                    for (int su = 0; su < 2; su++)
                        mma_f16(acc[mi][p * 2 + su], af[mi], &bf[su * 2]);
            }
        }
        __syncthreads();
    }

#pragma unroll
    for (int mi = 0; mi < 2; mi++)
#pragma unroll
        for (int ni = 0; ni < 8; ni++) {
            int e = n0 + wn + ni * 8 + (lane & 3) * 2;
            int h = e >> 6, d = e & 63;
#pragma unroll
            for (int rr = 0; rr < 2; rr++) {
                int t = t0 + wm + mi * 16 + (lane >> 2) + rr * 8;
                int m = t >> 8, i = t & 255;
                int idx = ((h * NM + m) * LQ + i) * DHH + d;
                *(uint32_t*)&outp[idx] =
                    pack_f16(acc[mi][ni][rr * 2 + 0], acc[mi][ni][rr * 2 + 1]);
            }
        }
}

// ============================================================================
// K2: e2[i][hm][j] fp16 single-pass, fp16 output. CTA 128x128, K=64 one-shot.
// ============================================================================
#define E4_ASZ (128 * 144)    // 18432
#define E4_TOT (2 * E4_ASZ)   // 36864

__global__ __launch_bounds__(256) void e2_mma_kernel()
{
    extern __shared__ __align__(16) unsigned char dsm[];
    const uint32_t sb = smem_to_u32(dsm);

    const int tid = threadIdx.x, lane = tid & 31, wid = tid >> 5;
    const int hm0 = blockIdx.x * 128;
    const int j0  = blockIdx.y * 128;
    const int i   = blockIdx.z;
    const int wm = (wid & 3) * 32;
    const int wn = (wid >> 2) * 64;

#pragma unroll
    for (int l = 0; l < 4; l++) {
        int id = tid + l * 256;
        int r = id >> 3, c = id & 7;
        cp16(sb + r * 144 + c * 16, &g_q16[((hm0 + r) * LQ + i) * DHH + c * 8]);
        cp16(sb + E4_ASZ + r * 144 + c * 16,
             &g_ak16[(i * LQ + j0 + r) * DHH + c * 8]);
    }
    CP_COMMIT();
    CP_WAIT(0);
    __syncthreads();

    float acc[2][8][4];
#pragma unroll
    for (int a = 0; a < 2; a++)
#pragma unroll
        for (int b = 0; b < 8; b++)
#pragma unroll
            for (int c = 0; c < 4; c++) acc[a][b][c] = 0.f;

#pragma unroll
    for (int s = 0; s < 4; s++) {
        uint32_t af[2][4];
#pragma unroll
        for (int mi = 0; mi < 2; mi++) {
            uint32_t ad = sb + (wm + mi * 16 + (lane & 15)) * 144 +
                          s * 32 + ((lane >> 4) & 1) * 16;
            ldsm_x4(ad, af[mi]);
        }
#pragma unroll
        for (int p = 0; p < 4; p++) {
            uint32_t bf[4];
            uint32_t bd = sb + E4_ASZ +
                (wn + p * 16 + (lane & 7) + ((lane >> 4) & 1) * 8) * 144 +
                s * 32 + ((lane >> 3) & 1) * 16;
            ldsm_x4(bd, bf);
#pragma unroll
            for (int mi = 0; mi < 2; mi++)
#pragma unroll
                for (int su = 0; su < 2; su++)
                    mma_f16(acc[mi][p * 2 + su], af[mi], &bf[su * 2]);
        }
    }

#pragma unroll
    for (int mi = 0; mi < 2; mi++)
#pragma unroll
        for (int ni = 0; ni < 8; ni++) {
            int j = j0 + wn + ni * 8 + (lane & 3) * 2;
#pragma unroll
            for (int rr = 0; rr < 2; rr++) {
                int hm = hm0 + wm + mi * 16 + (lane >> 2) + rr * 8;
                *(uint32_t*)&g_e16[(i * NSL + hm) * LQ + j] =
                    pack_f16(acc[mi][ni][rr * 2 + 0], acc[mi][ni][rr * 2 + 1]);
            }
        }
}

// ============================================================================
// K3: fused attention, fp16 single-pass; e2 read as fp16
// ============================================================================
#define A4_KSZ  (64 * 144)           // 9216
#define A4_STG  (2 * A4_KSZ)         // 18432
#define A4_Q    (2 * A4_STG)         // 36864
#define A4_QSZ  (128 * 144)          // 18432
#define A4_TOT  (A4_Q + A4_QSZ)      // 55296

__global__ __launch_bounds__(256) void attn_mma_kernel()
{
    extern __shared__ __align__(16) unsigned char dsm[];
    const uint32_t sb = smem_to_u32(dsm);
    const int tid = threadIdx.x, lane = tid & 31, wid = tid >> 5;
    const int i0 = blockIdx.x * 128;
    const int hm = blockIdx.y;
    const int wm = wid * 16;
    const int gr = lane >> 2, qd = lane & 3;

    auto load_kv = [&](int jc, int st) {
        uint32_t s0 = sb + st * A4_STG;
#pragma unroll
        for (int l = 0; l < 2; l++) {
            int id = tid + l * 256;
            int r = id >> 3, c = id & 7;
            int gk = (hm * LQ + jc * 64 + r) * DHH + c * 8;
            cp16(s0 + r * 144 + c * 16, &g_k16[gk]);
            cp16(s0 + A4_KSZ + r * 144 + c * 16, &g_v16[gk]);
        }
    };

    // Q resident
#pragma unroll
    for (int l = 0; l < 4; l++) {
        int id = tid + l * 256;
        int r = id >> 3, c = id & 7;
        cp16(sb + A4_Q + r * 144 + c * 16,
             &g_q16[(hm * LQ + i0 + r) * DHH + c * 8]);
    }
    CP_COMMIT();
    load_kv(0, 0);
    CP_COMMIT();

    float accz[8][4];
#pragma unroll
    for (int b = 0; b < 8; b++)
#pragma unroll
        for (int c = 0; c < 4; c++) accz[b][c] = 0.f;
    float rsum[2] = {0.f, 0.f};

    for (int jc = 0; jc < 4; jc++) {
        const int st = jc & 1;
        __syncthreads();
        if (jc < 3) { load_kv(jc + 1, st ^ 1); CP_COMMIT(); CP_WAIT(1); }
        else        { CP_WAIT(0); }
        __syncthreads();

        const uint32_t s0 = sb + st * A4_STG;

        // ---- scores: e1 = q k^T ----
        float acc[8][4];
#pragma unroll
        for (int b = 0; b < 8; b++)
#pragma unroll
            for (int c = 0; c < 4; c++) acc[b][c] = 0.f;

#pragma unroll
        for (int s = 0; s < 4; s++) {
            uint32_t af[4];
            uint32_t ad = sb + A4_Q + (wm + (lane & 15)) * 144 +
                          s * 32 + ((lane >> 4) & 1) * 16;
            ldsm_x4(ad, af);
#pragma unroll
            for (int p = 0; p < 4; p++) {
                uint32_t bf[4];
                uint32_t bd = s0 + (p * 16 + (lane & 7) + ((lane >> 4) & 1) * 8) * 144 +
                              s * 32 + ((lane >> 3) & 1) * 16;
                ldsm_x4(bd, bf);
#pragma unroll
                for (int su = 0; su < 2; su++)
                    mma_f16(acc[p * 2 + su], af, &bf[su * 2]);
            }
        }

        // ---- + e2(fp16), scale, exp, rowsum, pack p fp16 ----
        uint32_t pf[8][2];
        {
            int ir0 = i0 + wm + gr;
            __half2 e2b0[8], e2b1[8];
#pragma unroll
            for (int ni = 0; ni < 8; ni++) {
                int col = jc * 64 + ni * 8 + qd * 2;
                e2b0[ni] = *(const __half2*)&g_e16[(ir0 * NSL + hm) * LQ + col];
                e2b1[ni] = *(const __half2*)&g_e16[((ir0 + 8) * NSL + hm) * LQ + col];
            }
#pragma unroll
            for (int ni = 0; ni < 8; ni++) {
                int col = jc * 64 + ni * 8 + qd * 2;
                float e0 = __expf((acc[ni][0] + __half2float(e2b0[ni].x)) * 0.125f);
                float e1 = __expf((acc[ni][1] + __half2float(e2b0[ni].y)) * 0.125f);
                float e2v = __expf((acc[ni][2] + __half2float(e2b1[ni].x)) * 0.125f);
                float e3 = __expf((acc[ni][3] + __half2float(e2b1[ni].y)) * 0.125f);
                rsum[0] += e0 + e1;
                rsum[1] += e2v + e3;
                uint32_t p01 = pack_f16(e0, e1);
                uint32_t p23 = pack_f16(e2v, e3);
                pf[ni][0] = p01; pf[ni][1] = p23;
                *(uint32_t*)&g_a16[(ir0 * NSL + hm) * LQ + col] = p01;
                *(uint32_t*)&g_a16[((ir0 + 8) * NSL + hm) * LQ + col] = p23;
            }
        }

        // ---- z1 += p V ----
#pragma unroll
        for (int s = 0; s < 4; s++) {
            uint32_t Af[4] = {pf[2 * s][0], pf[2 * s][1],
                              pf[2 * s + 1][0], pf[2 * s + 1][1]};
#pragma unroll
            for (int p = 0; p < 4; p++) {
                uint32_t bf[4];
                uint32_t bd = s0 + A4_KSZ + (s * 16 + (lane & 15)) * 144 +
                              p * 32 + ((lane >> 4) & 1) * 16;
                ldsm_x4_t(bd, bf);
#pragma unroll
                for (int su = 0; su < 2; su++)
                    mma_f16(accz[p * 2 + su], Af, &bf[su * 2]);
            }
        }
    }

    // ---- finalize ----
    float inv[2];
#pragma unroll
    for (int rr = 0; rr < 2; rr++) {
        float r = rsum[rr];
        r += __shfl_xor_sync(0xffffffffu, r, 1);
        r += __shfl_xor_sync(0xffffffffu, r, 2);
        inv[rr] = 1.f / r;
    }
    if (qd == 0) {
#pragma unroll
        for (int rr = 0; rr < 2; rr++)
            g_invl[hm * LQ + i0 + wm + gr + rr * 8] = inv[rr];
    }
#pragma unroll
    for (int ni = 0; ni < 8; ni++)
#pragma unroll
        for (int rr = 0; rr < 2; rr++) {
            int ir = i0 + wm + gr + rr * 8;
            int d = ni * 8 + qd * 2;
            *(float2*)&g_z1[(hm * LQ + ir) * DHH + d] =
                make_float2(accz[ni][rr * 2 + 0] * inv[rr],
                            accz[ni][rr * 2 + 1] * inv[rr]);
        }
}

// ============================================================================
// K4: z2 GEMM fp16 single-pass, 2-stage double buffer, invl in reduction
// ============================================================================
#define Z5_ASZ  (128 * 144)          // 18432
#define Z5_BSZ  (64 * 144)           // 9216
#define Z5_STG  (Z5_ASZ + Z5_BSZ)    // 27648
#define Z5_LINV (2 * Z5_STG)         // 55296
#define Z5_TOT  (Z5_LINV + 512)      // 55808

__global__ __launch_bounds__(256) void z2_mma_kernel()
{
    extern __shared__ __align__(16) unsigned char dsm[];
    const uint32_t sb = smem_to_u32(dsm);
    const int tid = threadIdx.x, lane = tid & 31, wid = tid >> 5;
    const int hm0 = blockIdx.x * 128;
    const int i = blockIdx.y;
    const int wm = wid * 16;
    float* linv = (float*)(dsm + Z5_LINV);

    if (tid < 128) linv[tid] = g_invl[(hm0 + tid) * LQ + i];

    auto load_chunk = [&](int jc, int st) {
        uint32_t s0 = sb + st * Z5_STG;
#pragma unroll
        for (int l = 0; l < 4; l++) {
            int id = tid + l * 256;
            int r = id >> 3, c = id & 7;
            cp16(s0 + r * 144 + c * 16,
                 &g_a16[(i * NSL + hm0 + r) * LQ + jc * 64 + c * 8]);
        }
#pragma unroll
        for (int l = 0; l < 2; l++) {
            int id = tid + l * 256;
            int r = id >> 3, c = id & 7;
            cp16(s0 + Z5_ASZ + r * 144 + c * 16,
                 &g_av16[(i * LQ + jc * 64 + r) * DHH + c * 8]);
        }
    };

    load_chunk(0, 0);
    CP_COMMIT();

    float acc[8][4];
#pragma unroll
    for (int b = 0; b < 8; b++)
#pragma unroll
        for (int c = 0; c < 4; c++) acc[b][c] = 0.f;

    for (int jc = 0; jc < 4; jc++) {
        const int st = jc & 1;
        __syncthreads();
        if (jc < 3) { load_chunk(jc + 1, st ^ 1); CP_COMMIT(); CP_WAIT(1); }
        else        { CP_WAIT(0); }
        __syncthreads();

        const uint32_t s0 = sb + st * Z5_STG;
#pragma unroll
        for (int s = 0; s < 4; s++) {
            uint32_t af[4];
            uint32_t ad = s0 + (wm + (lane & 15)) * 144 +
                          s * 32 + ((lane >> 4) & 1) * 16;
            ldsm_x4(ad, af);
#pragma unroll
            for (int p = 0; p < 4; p++) {
                uint32_t bf[4];
                uint32_t bd = s0 + Z5_ASZ + (s * 16 + (lane & 15)) * 144 +
                              p * 32 + ((lane >> 4) & 1) * 16;
                ldsm_x4_t(bd, bf);
#pragma unroll
                for (int su = 0; su < 2; su++)
                    mma_f16(acc[p * 2 + su], af, &bf[su * 2]);
            }
        }
    }

    // reduce over m (2 h-groups of 64) with invl scaling
    __syncthreads();
    float* Sf = (float*)dsm;   // [128][65]
#pragma unroll
    for (int ni = 0; ni < 8; ni++)
#pragma unroll
        for (int rr = 0; rr < 2; rr++) {
            int r = wm + (lane >> 2) + rr * 8;
            int c = ni * 8 + (lane & 3) * 2;
            Sf[r * 65 + c]     = acc[ni][rr * 2 + 0];
            Sf[r * 65 + c + 1] = acc[ni][rr * 2 + 1];
        }
    __syncthreads();
    if (tid < 128) {
        int g = tid >> 6, d = tid & 63;
        float s = 0.f;
#pragma unroll 8
        for (int m = 0; m < 64; m++)
            s += Sf[(g * 64 + m) * 65 + d] * linv[g * 64 + m];
        int h = blockIdx.x * 2 + g;
        g_z2[(i * NH + h) * DHH + d] = s;
    }
}

// =============================================================================
// K5: out
// =============================================================================
__global__ __launch_bounds__(256) void final_kernel(float* __restrict__ out)
{
    int g = blockIdx.x * 256 + threadIdx.x;
    int i = g >> 9;
    int rest = g & 511;
    int h = rest >> 6;
    int d = rest & 63;

    const float* zp = &g_z1[((h * NM) * LQ + i) * DHH + d];
    float s = g_z2[(i * NH + h) * DHH + d];
#pragma unroll 8
    for (int m = 0; m < 64; m++) s += zp[m * (LQ * DHH)];
    out[g] = s;
}

// =============================================================================
extern "C" void kernel_launch(void* const* d_in, const int* in_sizes, int n_in,
                              void* d_out, int out_size)
{
    const float* x  = (const float*)d_in[0];
    const float* Wq = (const float*)d_in[1];
    const float* Wk = (const float*)d_in[2];
    const float* Wv = (const float*)d_in[3];
    const float* aK = (const float*)d_in[4];
    const float* aV = (const float*)d_in[5];
    float* out = (float*)d_out;

    cudaFuncSetAttribute(proj_mma_kernel,
                         cudaFuncAttributeMaxDynamicSharedMemorySize, P_TOT);
    cudaFuncSetAttribute(e2_mma_kernel,
                         cudaFuncAttributeMaxDynamicSharedMemorySize, E4_TOT);
    cudaFuncSetAttribute(attn_mma_kernel,
                         cudaFuncAttributeMaxDynamicSharedMemorySize, A4_TOT);
    cudaFuncSetAttribute(z2_mma_kernel,
                         cudaFuncAttributeMaxDynamicSharedMemorySize, Z5_TOT);

    void *x_p, *w_p, *ak_p, *av_p;
    cudaGetSymbolAddress(&x_p,  g_x16);
    cudaGetSymbolAddress(&w_p,  g_w16);
    cudaGetSymbolAddress(&ak_p, g_ak16);
    cudaGetSymbolAddress(&av_p, g_av16);

    SplitArgs sa;
    sa.src[0] = x;  sa.dst[0] = (__half*)x_p;
    sa.src[1] = Wq; sa.dst[1] = (__half*)w_p;
    sa.src[2] = Wk; sa.dst[2] = (__half*)w_p + DMOD * DMOD;
    sa.src[3] = Wv; sa.dst[3] = (__half*)w_p + 2 * DMOD * DMOD;
    sa.src[4] = aK; sa.dst[4] = (__half*)ak_p;
    sa.src[5] = aV; sa.dst[5] = (__half*)av_p;
    int nv[6] = {NTOK * DMOD / 4, DMOD * DMOD / 4, DMOD * DMOD / 4,
                 DMOD * DMOD / 4, LQ * LQ * DHH / 4, LQ * LQ * DHH / 4};
    sa.off[0] = 0;
    for (int s = 0; s < 6; s++) sa.off[s + 1] = sa.off[s] + nv[s];

    split_all_kernel<<<4096, 256>>>(sa);

    proj_mma_kernel<<<dim3(NTOK / 128, DMOD / 128, 3), 256, P_TOT>>>();
    e2_mma_kernel<<<dim3(4, 2, LQ), 256, E4_TOT>>>();
    attn_mma_kernel<<<dim3(2, NSL), 256, A4_TOT>>>();
    z2_mma_kernel<<<dim3(4, LQ), 256, Z5_TOT>>>();
    final_kernel<<<512, 256>>>(out);
}